// round 1
// baseline (speedup 1.0000x reference)
#include <cuda_runtime.h>

// ---------------------------------------------------------------------------
// GNN_EBM reduced-form kernel.
//
// Reference math collapses (see analysis): since h is node-uniform before the
// graph convs and A >= 0, both conv layers reduce to per-node positive scalars
// c_i applied to r0 = relu(z @ Win^T + bin). Only nodes 100 (T head) and 101
// (Y head) are consumed, so:
//   out[b] = MLP_T(c100 * r0[b]) + MLP_Y(c101 * r0[b])
// with MLP(h) = relu(h @ W1^T + b1) @ w2 + b2.
// ---------------------------------------------------------------------------

#define BATCH  2048
#define DX     100
#define DN     102     // d_nodes
#define HID    256
#define MH     128     // mlp hidden
#define BT     16      // batch rows per block
#define NBLK   (BATCH / BT)   // 128
#define REDS   132     // padded stride for reduction buffer (bank-friendly)

__device__ float g_c[2];   // c100 (T branch), c101 (Y branch)

__device__ __forceinline__ float sigm(float v) {
    return 1.0f / (1.0f + __expf(-v));
}

// ---------------------------------------------------------------------------
// Kernel 0: compute c_i = 1 + s_i + (1/N) * sum_j A[i,j]*(1+s_j), i in {100,101}
// A[i,j] = sigmoid(B[i,j]) * mask[i,j];  mask: no diag, row 101 only col 100.
// ---------------------------------------------------------------------------
__global__ void prep_kernel(const float* __restrict__ B) {
    __shared__ float s[DN];
    const float inv_n = 1.0f / (float)DN;
    int j = threadIdx.x;
    if (j < DN) {
        float acc = 0.0f;
        if (j == DN - 1) {
            // last row: cols [0,DX) masked, diag masked -> only col DN-2 (=100)
            acc = sigm(B[j * DN + (DN - 2)]);
        } else {
            #pragma unroll 4
            for (int k = 0; k < DN; k++) {
                if (k == j) continue;
                acc += sigm(B[j * DN + k]);
            }
        }
        s[j] = acc * inv_n;
    }
    __syncthreads();
    if (j < 2) {
        int i = (DN - 2) + j;   // 100 or 101
        float acc = 0.0f;
        if (i == DN - 1) {
            float a = sigm(B[i * DN + (DN - 2)]);
            acc = a * (1.0f + s[DN - 2]);
        } else {
            #pragma unroll 4
            for (int k = 0; k < DN; k++) {
                if (k == i) continue;
                float a = sigm(B[i * DN + k]);
                acc += a * (1.0f + s[k]);
            }
        }
        g_c[j] = 1.0f + s[i] + acc * inv_n;
    }
}

// ---------------------------------------------------------------------------
// Kernel 1: fused r0 GEMM + two head MLPs, batch-tiled (BT rows / block).
// 256 threads. All shared-memory reads are warp-uniform (broadcast).
// ---------------------------------------------------------------------------

#define FMA16(W, BASE)                                            \
    {                                                             \
        const float4* _p = (const float4*)(BASE);                 \
        float4 _a0 = _p[0], _a1 = _p[1], _a2 = _p[2], _a3 = _p[3];\
        acc[0]  = fmaf((W), _a0.x, acc[0]);                       \
        acc[1]  = fmaf((W), _a0.y, acc[1]);                       \
        acc[2]  = fmaf((W), _a0.z, acc[2]);                       \
        acc[3]  = fmaf((W), _a0.w, acc[3]);                       \
        acc[4]  = fmaf((W), _a1.x, acc[4]);                       \
        acc[5]  = fmaf((W), _a1.y, acc[5]);                       \
        acc[6]  = fmaf((W), _a1.z, acc[6]);                       \
        acc[7]  = fmaf((W), _a1.w, acc[7]);                       \
        acc[8]  = fmaf((W), _a2.x, acc[8]);                       \
        acc[9]  = fmaf((W), _a2.y, acc[9]);                       \
        acc[10] = fmaf((W), _a2.z, acc[10]);                      \
        acc[11] = fmaf((W), _a2.w, acc[11]);                      \
        acc[12] = fmaf((W), _a3.x, acc[12]);                      \
        acc[13] = fmaf((W), _a3.y, acc[13]);                      \
        acc[14] = fmaf((W), _a3.z, acc[14]);                      \
        acc[15] = fmaf((W), _a3.w, acc[15]);                      \
    }

#define FMA8(W, BASE)                                             \
    {                                                             \
        const float4* _p = (const float4*)(BASE);                 \
        float4 _a0 = _p[0], _a1 = _p[1];                          \
        macc[0] = fmaf((W), _a0.x, macc[0]);                      \
        macc[1] = fmaf((W), _a0.y, macc[1]);                      \
        macc[2] = fmaf((W), _a0.z, macc[2]);                      \
        macc[3] = fmaf((W), _a0.w, macc[3]);                      \
        macc[4] = fmaf((W), _a1.x, macc[4]);                      \
        macc[5] = fmaf((W), _a1.y, macc[5]);                      \
        macc[6] = fmaf((W), _a1.z, macc[6]);                      \
        macc[7] = fmaf((W), _a1.w, macc[7]);                      \
    }

__global__ __launch_bounds__(256) void fused_kernel(
    const float* __restrict__ x,  const float* __restrict__ tt,
    const float* __restrict__ yy,
    const float* __restrict__ Win, const float* __restrict__ bin,
    const float* __restrict__ WT1, const float* __restrict__ bT1,
    const float* __restrict__ wT2, const float* __restrict__ bT2,
    const float* __restrict__ WY1, const float* __restrict__ bY1,
    const float* __restrict__ wY2, const float* __restrict__ bY2,
    float* __restrict__ out)
{
    __shared__ __align__(16) float z_s[DN * BT];    // [k][r] transposed z tile
    __shared__ __align__(16) float r0_s[HID * BT];  // [hid][r]
    __shared__ float red_s[BT * REDS];              // per-row partials for head dot
    __shared__ float rowacc[BT];

    const int t  = threadIdx.x;
    const int b0 = blockIdx.x * BT;

    const float c0 = g_c[0];
    const float c1 = g_c[1];

    // ---- load z tile, transposed: z_s[k*BT + r] = z[b0+r][k] ----
    for (int idx = t; idx < DN * BT; idx += 256) {
        int k = idx / BT;
        int r = idx - k * BT;
        int b = b0 + r;
        float v;
        if (k < DX)       v = x[b * DX + k];
        else if (k == DX) v = tt[b];
        else              v = yy[b];
        z_s[idx] = v;
    }
    __syncthreads();

    // ---- stage A: r0[b0+r][t] = relu(dot(z[r], Win[t]) + bin[t]) ----
    {
        float acc[BT];
        #pragma unroll
        for (int r = 0; r < BT; r++) acc[r] = 0.0f;

        const float* wr = Win + t * DN;
        #pragma unroll 3
        for (int k = 0; k < DN; k += 2) {
            float w0 = __ldg(wr + k);
            float w1 = __ldg(wr + k + 1);
            FMA16(w0, z_s + k * BT);
            FMA16(w1, z_s + (k + 1) * BT);
        }

        float bc = __ldg(bin + t);
        #pragma unroll
        for (int r = 0; r < BT; r++)
            r0_s[t * BT + r] = fmaxf(acc[r] + bc, 0.0f);
    }
    __syncthreads();

    // ---- stage B: two head MLPs ----
    const int j    = t & (MH - 1);  // mlp-hidden index
    const int half = t >> 7;        // 0: rows 0..7, 1: rows 8..15
    const int rb   = half * 8;

    for (int br = 0; br < 2; br++) {
        const float* W1 = br ? WY1 : WT1;
        const float* b1 = br ? bY1 : bT1;
        const float* w2 = br ? wY2 : wT2;
        const float  cs = br ? c1 : c0;

        float macc[8];
        #pragma unroll
        for (int r = 0; r < 8; r++) macc[r] = 0.0f;

        const float* wr = W1 + j * HID;
        #pragma unroll 4
        for (int k = 0; k < HID; k += 2) {
            float w0 = __ldg(wr + k);
            float w1 = __ldg(wr + k + 1);
            FMA8(w0, r0_s + k * BT + rb);
            FMA8(w1, r0_s + (k + 1) * BT + rb);
        }

        float b1j = __ldg(b1 + j);
        float w2j = __ldg(w2 + j);
        #pragma unroll
        for (int r = 0; r < 8; r++) {
            float m = fmaxf(fmaf(cs, macc[r], b1j), 0.0f);
            red_s[(rb + r) * REDS + j] = m * w2j;
        }
        __syncthreads();

        if (t < BT) {
            float s = 0.0f;
            #pragma unroll 8
            for (int jj = 0; jj < MH; jj++) s += red_s[t * REDS + jj];
            if (br == 0) {
                rowacc[t] = s;
            } else {
                out[b0 + t] = rowacc[t] + s + __ldg(bT2) + __ldg(bY2);
            }
        }
        __syncthreads();
    }
}

// ---------------------------------------------------------------------------
extern "C" void kernel_launch(void* const* d_in, const int* in_sizes, int n_in,
                              void* d_out, int out_size)
{
    const float* x    = (const float*)d_in[0];
    const float* tt   = (const float*)d_in[1];
    const float* yy   = (const float*)d_in[2];
    const float* Bprm = (const float*)d_in[3];
    const float* Win  = (const float*)d_in[4];
    const float* bin  = (const float*)d_in[5];
    const float* WT1  = (const float*)d_in[6];
    const float* bT1  = (const float*)d_in[7];
    const float* wT2  = (const float*)d_in[8];
    const float* bT2  = (const float*)d_in[9];
    const float* WY1  = (const float*)d_in[10];
    const float* bY1  = (const float*)d_in[11];
    const float* wY2  = (const float*)d_in[12];
    const float* bY2  = (const float*)d_in[13];
    float* out = (float*)d_out;

    prep_kernel<<<1, 128>>>(Bprm);
    fused_kernel<<<NBLK, 256>>>(x, tt, yy, Win, bin,
                                WT1, bT1, wT2, bT2,
                                WY1, bY1, wY2, bY2, out);
}

// round 2
// speedup vs baseline: 1.3184x; 1.3184x over previous
#include <cuda_runtime.h>

// ---------------------------------------------------------------------------
// GNN_EBM reduced form:
//   out[b] = MLP_T(c100 * r0[b]) + MLP_Y(c101 * r0[b]),
//   r0 = relu(z @ Win^T + bin),  z = [x|t|y], c_i from sigmoid(B)*mask rowsums.
//
// Round-2 structure:
//   K1 (prep): c-scalars + tile-transpose Win/WT1/WY1 into k-major scratch.
//   K2 (fused): register-tiled fp32 GEMM chain, fully coalesced weight LDGs,
//               broadcast/conflict-free smem.
// ---------------------------------------------------------------------------

#define BATCH  2048
#define DX     100
#define DN     102
#define DNP    104          // padded K for stage A
#define HID    256
#define MH     128
#define BT     16           // batch rows per block
#define NBLK   (BATCH / BT) // 128
#define ZS     104          // z_s row stride (floats), %4==0
#define RS     260          // r0_s row stride (floats), %4==0

__device__ float g_c[2];
__device__ float g_WinT[DNP * HID];    // [k][h]   (rows 102,103 zero)
__device__ float g_WT1T[HID * MH];     // [k][h]
__device__ float g_WY1T[HID * MH];     // [k][h]

__device__ __forceinline__ float sigm(float v) {
    return 1.0f / (1.0f + __expf(-v));
}

// ---------------------------------------------------------------------------
// K1: blocks 0..31: Win tiles, 32..63: WT1, 64..95: WY1, 96: c-scalars.
// 32x32 smem tile transpose, coalesced on both sides.
// ---------------------------------------------------------------------------
__global__ __launch_bounds__(256) void prep_kernel(
    const float* __restrict__ B,
    const float* __restrict__ Win,
    const float* __restrict__ WT1,
    const float* __restrict__ WY1)
{
    __shared__ float tile[32][33];
    __shared__ float s[DN];

    const int b = blockIdx.x;
    const int t = threadIdx.x;

    if (b < 96) {
        const float* src;
        float* dst;
        int R, C, Rd, Cd, r0, c0;
        if (b < 32) {              // Win [256][102] -> WinT [104][256]
            src = Win; dst = g_WinT; R = HID; C = DN; Rd = DNP; Cd = HID;
            int idx = b;           // 8 row-tiles x 4 col-tiles
            r0 = (idx >> 2) * 32; c0 = (idx & 3) * 32;
        } else if (b < 64) {       // WT1 [128][256] -> [256][128]
            src = WT1; dst = g_WT1T; R = MH; C = HID; Rd = HID; Cd = MH;
            int idx = b - 32;      // 4 x 8
            r0 = (idx >> 3) * 32; c0 = (idx & 7) * 32;
        } else {                   // WY1
            src = WY1; dst = g_WY1T; R = MH; C = HID; Rd = HID; Cd = MH;
            int idx = b - 64;
            r0 = (idx >> 3) * 32; c0 = (idx & 7) * 32;
        }
        const int tx = t & 31, ty = t >> 5;   // 32 x 8
        #pragma unroll
        for (int i = 0; i < 4; i++) {
            int r = r0 + ty + i * 8;
            int c = c0 + tx;
            float v = (r < R && c < C) ? src[r * C + c] : 0.0f;
            tile[ty + i * 8][tx] = v;
        }
        __syncthreads();
        #pragma unroll
        for (int i = 0; i < 4; i++) {
            int rd = c0 + ty + i * 8;  // dst row = src col
            int cd = r0 + tx;          // dst col = src row
            if (rd < Rd && cd < Cd)
                dst[rd * Cd + cd] = tile[tx][ty + i * 8];
        }
        return;
    }

    // ---- block 96: c scalars ----
    const float inv_n = 1.0f / (float)DN;
    int j = t;
    if (j < DN) {
        float acc = 0.0f;
        if (j == DN - 1) {
            acc = sigm(B[j * DN + (DN - 2)]);
        } else {
            #pragma unroll 4
            for (int k = 0; k < DN; k++) {
                if (k == j) continue;
                acc += sigm(B[j * DN + k]);
            }
        }
        s[j] = acc * inv_n;
    }
    __syncthreads();
    if (j < 2) {
        int i = (DN - 2) + j;
        float acc = 0.0f;
        if (i == DN - 1) {
            acc = sigm(B[i * DN + (DN - 2)]) * (1.0f + s[DN - 2]);
        } else {
            #pragma unroll 4
            for (int k = 0; k < DN; k++) {
                if (k == i) continue;
                acc += sigm(B[i * DN + k]) * (1.0f + s[k]);
            }
        }
        g_c[j] = 1.0f + s[i] + acc * inv_n;
    }
}

// ---------------------------------------------------------------------------
// K2: fused r0 GEMM + two head MLPs.  256 threads, BT=16 rows per block.
// ---------------------------------------------------------------------------
__global__ __launch_bounds__(256) void fused_kernel(
    const float* __restrict__ x,  const float* __restrict__ tt,
    const float* __restrict__ yy, const float* __restrict__ bin,
    const float* __restrict__ bT1, const float* __restrict__ wT2,
    const float* __restrict__ bT2,
    const float* __restrict__ bY1, const float* __restrict__ wY2,
    const float* __restrict__ bY2,
    float* __restrict__ out)
{
    __shared__ __align__(16) float z_s[BT * ZS];    // [r][k], k padded->104, pads zeroed
    __shared__ __align__(16) float r0_s[BT * RS];   // [r][hid]
    __shared__ float red_s[2][BT];

    const int t  = threadIdx.x;
    const int b0 = blockIdx.x * BT;

    // ---- load z tile [r][k] (coalesced along k), zero pads ----
    for (int idx = t; idx < BT * ZS; idx += 256) {
        int r = idx / ZS;
        int k = idx - r * ZS;
        int b = b0 + r;
        float v = 0.0f;
        if (k < DX)            v = x[b * DX + k];
        else if (k == DX)      v = tt[b];
        else if (k == DX + 1)  v = yy[b];
        z_s[idx] = v;
    }
    __syncthreads();

    // ---- stage A: r0 = relu(z @ Win^T + bin) ----
    {
        const int hn = t & 63;    // h = 4*hn  (0..255)
        const int rm = t >> 6;    // r = 4*rm  (0..15)
        float acc[4][4];
        #pragma unroll
        for (int i = 0; i < 4; i++)
            #pragma unroll
            for (int j = 0; j < 4; j++) acc[i][j] = 0.0f;

        const float4* wt = (const float4*)g_WinT + hn;      // + k*64 per row
        const float*  zb = z_s + 4 * rm * ZS;

        #pragma unroll 2
        for (int k = 0; k < DNP; k += 4) {
            float4 wv[4];
            #pragma unroll
            for (int kk = 0; kk < 4; kk++) wv[kk] = wt[(k + kk) * (HID / 4)];
            float4 zv[4];
            #pragma unroll
            for (int rr = 0; rr < 4; rr++)
                zv[rr] = *(const float4*)(zb + rr * ZS + k);
            #pragma unroll
            for (int rr = 0; rr < 4; rr++) {
                float z0 = zv[rr].x, z1 = zv[rr].y, z2 = zv[rr].z, z3 = zv[rr].w;
                acc[rr][0] = fmaf(z0, wv[0].x, acc[rr][0]);
                acc[rr][1] = fmaf(z0, wv[0].y, acc[rr][1]);
                acc[rr][2] = fmaf(z0, wv[0].z, acc[rr][2]);
                acc[rr][3] = fmaf(z0, wv[0].w, acc[rr][3]);
                acc[rr][0] = fmaf(z1, wv[1].x, acc[rr][0]);
                acc[rr][1] = fmaf(z1, wv[1].y, acc[rr][1]);
                acc[rr][2] = fmaf(z1, wv[1].z, acc[rr][2]);
                acc[rr][3] = fmaf(z1, wv[1].w, acc[rr][3]);
                acc[rr][0] = fmaf(z2, wv[2].x, acc[rr][0]);
                acc[rr][1] = fmaf(z2, wv[2].y, acc[rr][1]);
                acc[rr][2] = fmaf(z2, wv[2].z, acc[rr][2]);
                acc[rr][3] = fmaf(z2, wv[2].w, acc[rr][3]);
                acc[rr][0] = fmaf(z3, wv[3].x, acc[rr][0]);
                acc[rr][1] = fmaf(z3, wv[3].y, acc[rr][1]);
                acc[rr][2] = fmaf(z3, wv[3].z, acc[rr][2]);
                acc[rr][3] = fmaf(z3, wv[3].w, acc[rr][3]);
            }
        }

        float4 bv = *(const float4*)(bin + 4 * hn);
        #pragma unroll
        for (int rr = 0; rr < 4; rr++) {
            float4 o;
            o.x = fmaxf(acc[rr][0] + bv.x, 0.0f);
            o.y = fmaxf(acc[rr][1] + bv.y, 0.0f);
            o.z = fmaxf(acc[rr][2] + bv.z, 0.0f);
            o.w = fmaxf(acc[rr][3] + bv.w, 0.0f);
            *(float4*)(r0_s + (4 * rm + rr) * RS + 4 * hn) = o;
        }
    }
    __syncthreads();

    // ---- stage B: both head MLPs (branch = t>>7) ----
    {
        const int br  = t >> 7;          // 0: T, 1: Y
        const int hn2 = t & 31;          // h = 4*hn2 (0..127); == lane id
        const int rm2 = (t >> 5) & 3;    // r = 4*rm2 (0..15)

        const float* W1T = br ? g_WY1T : g_WT1T;
        const float* b1p = br ? bY1 : bT1;
        const float* w2p = br ? wY2 : wT2;
        const float  cs  = g_c[br];

        float acc[4][4];
        #pragma unroll
        for (int i = 0; i < 4; i++)
            #pragma unroll
            for (int j = 0; j < 4; j++) acc[i][j] = 0.0f;

        const float4* wt = (const float4*)W1T + hn2;         // + k*32 per row
        const float*  zb = r0_s + 4 * rm2 * RS;

        #pragma unroll 2
        for (int k = 0; k < HID; k += 4) {
            float4 wv[4];
            #pragma unroll
            for (int kk = 0; kk < 4; kk++) wv[kk] = wt[(k + kk) * (MH / 4)];
            float4 zv[4];
            #pragma unroll
            for (int rr = 0; rr < 4; rr++)
                zv[rr] = *(const float4*)(zb + rr * RS + k);
            #pragma unroll
            for (int rr = 0; rr < 4; rr++) {
                float z0 = zv[rr].x, z1 = zv[rr].y, z2 = zv[rr].z, z3 = zv[rr].w;
                acc[rr][0] = fmaf(z0, wv[0].x, acc[rr][0]);
                acc[rr][1] = fmaf(z0, wv[0].y, acc[rr][1]);
                acc[rr][2] = fmaf(z0, wv[0].z, acc[rr][2]);
                acc[rr][3] = fmaf(z0, wv[0].w, acc[rr][3]);
                acc[rr][0] = fmaf(z1, wv[1].x, acc[rr][0]);
                acc[rr][1] = fmaf(z1, wv[1].y, acc[rr][1]);
                acc[rr][2] = fmaf(z1, wv[1].z, acc[rr][2]);
                acc[rr][3] = fmaf(z1, wv[1].w, acc[rr][3]);
                acc[rr][0] = fmaf(z2, wv[2].x, acc[rr][0]);
                acc[rr][1] = fmaf(z2, wv[2].y, acc[rr][1]);
                acc[rr][2] = fmaf(z2, wv[2].z, acc[rr][2]);
                acc[rr][3] = fmaf(z2, wv[2].w, acc[rr][3]);
                acc[rr][0] = fmaf(z3, wv[3].x, acc[rr][0]);
                acc[rr][1] = fmaf(z3, wv[3].y, acc[rr][1]);
                acc[rr][2] = fmaf(z3, wv[3].z, acc[rr][2]);
                acc[rr][3] = fmaf(z3, wv[3].w, acc[rr][3]);
            }
        }

        float4 b1v = *(const float4*)(b1p + 4 * hn2);
        float4 w2v = *(const float4*)(w2p + 4 * hn2);
        float s[4];
        #pragma unroll
        for (int rr = 0; rr < 4; rr++) {
            float m0 = fmaxf(fmaf(cs, acc[rr][0], b1v.x), 0.0f);
            float m1 = fmaxf(fmaf(cs, acc[rr][1], b1v.y), 0.0f);
            float m2 = fmaxf(fmaf(cs, acc[rr][2], b1v.z), 0.0f);
            float m3 = fmaxf(fmaf(cs, acc[rr][3], b1v.w), 0.0f);
            s[rr] = fmaf(m0, w2v.x, fmaf(m1, w2v.y, fmaf(m2, w2v.z, m3 * w2v.w)));
        }
        #pragma unroll
        for (int off = 16; off > 0; off >>= 1) {
            #pragma unroll
            for (int rr = 0; rr < 4; rr++)
                s[rr] += __shfl_xor_sync(0xFFFFFFFFu, s[rr], off);
        }
        if (hn2 == 0) {
            #pragma unroll
            for (int rr = 0; rr < 4; rr++)
                red_s[br][4 * rm2 + rr] = s[rr];
        }
    }
    __syncthreads();

    if (t < BT)
        out[b0 + t] = red_s[0][t] + red_s[1][t] + bT2[0] + bY2[0];
}

// ---------------------------------------------------------------------------
extern "C" void kernel_launch(void* const* d_in, const int* in_sizes, int n_in,
                              void* d_out, int out_size)
{
    const float* x    = (const float*)d_in[0];
    const float* tt   = (const float*)d_in[1];
    const float* yy   = (const float*)d_in[2];
    const float* Bprm = (const float*)d_in[3];
    const float* Win  = (const float*)d_in[4];
    const float* bin  = (const float*)d_in[5];
    const float* WT1  = (const float*)d_in[6];
    const float* bT1  = (const float*)d_in[7];
    const float* wT2  = (const float*)d_in[8];
    const float* bT2  = (const float*)d_in[9];
    const float* WY1  = (const float*)d_in[10];
    const float* bY1  = (const float*)d_in[11];
    const float* wY2  = (const float*)d_in[12];
    const float* bY2  = (const float*)d_in[13];
    float* out = (float*)d_out;

    prep_kernel<<<97, 256>>>(Bprm, Win, WT1, WY1);
    fused_kernel<<<NBLK, 256>>>(x, tt, yy, bin,
                                bT1, wT2, bT2,
                                bY1, wY2, bY2, out);
}

// round 3
// speedup vs baseline: 1.9370x; 1.4692x over previous
#include <cuda_runtime.h>
#include <cstdint>

// ---------------------------------------------------------------------------
// GNN_EBM reduced form:
//   out[b] = MLP_T(c100 * r0[b]) + MLP_Y(c101 * r0[b]),
//   r0 = relu(z @ Win^T + bin),  z = [x|t|y], c_i from sigmoid(B)*mask rowsums.
//
// Round-3: 512-thread blocks (4 warps/SMSP), cp.async 3-buffer weight pipeline
// (smem-resident weights, no dependent global loads in the mainloop).
// ---------------------------------------------------------------------------

#define BATCH   2048
#define DX      100
#define DN      102
#define DNP     112            // stage-A K padded to KC multiple
#define HID     256
#define MH      128
#define BT      16             // batch rows per block
#define NBLK    (BATCH / BT)   // 128
#define THREADS 512
#define KC      8              // k rows per weight chunk
#define NCA     (DNP / KC)     // 14 stage-A chunks
#define NCB     (HID / KC)     // 32 stage-B chunks
#define NCH     (NCA + NCB)    // 46
#define ZS      112            // z_s row stride

__device__ float g_c[2];
__device__ float g_WinT[DNP * HID];   // [k][h], rows 102..111 zero
__device__ float g_WT1T[HID * MH];    // [k][h]
__device__ float g_WY1T[HID * MH];    // [k][h]

__device__ __forceinline__ float sigm(float v) {
    return 1.0f / (1.0f + __expf(-v));
}

__device__ __forceinline__ void cpasync16(void* dst, const void* src) {
    uint32_t d = (uint32_t)__cvta_generic_to_shared(dst);
    asm volatile("cp.async.cg.shared.global [%0], [%1], 16;\n"
                 :: "r"(d), "l"(src) : "memory");
}

// ---------------------------------------------------------------------------
// K1: blocks 0..31: Win tiles, 32..63: WT1, 64..95: WY1, 96: c-scalars.
// ---------------------------------------------------------------------------
__global__ __launch_bounds__(256) void prep_kernel(
    const float* __restrict__ B,
    const float* __restrict__ Win,
    const float* __restrict__ WT1,
    const float* __restrict__ WY1)
{
    __shared__ float tile[32][33];
    __shared__ float s[DN];

    const int b = blockIdx.x;
    const int t = threadIdx.x;

    if (b < 96) {
        const float* src;
        float* dst;
        int R, C, Rd, Cd, r0, c0;
        if (b < 32) {              // Win [256][102] -> WinT [112][256]
            src = Win; dst = g_WinT; R = HID; C = DN; Rd = DNP; Cd = HID;
            int idx = b;           // 8 row-tiles x 4 col-tiles
            r0 = (idx >> 2) * 32; c0 = (idx & 3) * 32;
        } else if (b < 64) {       // WT1 [128][256] -> [256][128]
            src = WT1; dst = g_WT1T; R = MH; C = HID; Rd = HID; Cd = MH;
            int idx = b - 32;      // 4 x 8
            r0 = (idx >> 3) * 32; c0 = (idx & 7) * 32;
        } else {                   // WY1
            src = WY1; dst = g_WY1T; R = MH; C = HID; Rd = HID; Cd = MH;
            int idx = b - 64;
            r0 = (idx >> 3) * 32; c0 = (idx & 7) * 32;
        }
        const int tx = t & 31, ty = t >> 5;   // 32 x 8
        #pragma unroll
        for (int i = 0; i < 4; i++) {
            int r = r0 + ty + i * 8;
            int c = c0 + tx;
            float v = (r < R && c < C) ? src[r * C + c] : 0.0f;
            tile[ty + i * 8][tx] = v;
        }
        __syncthreads();
        #pragma unroll
        for (int i = 0; i < 4; i++) {
            int rd = c0 + ty + i * 8;  // dst row = src col
            int cd = r0 + tx;          // dst col = src row
            if (rd < Rd && cd < Cd)
                dst[rd * Cd + cd] = tile[tx][ty + i * 8];
        }
        return;
    }

    // ---- block 96: c scalars ----
    const float inv_n = 1.0f / (float)DN;
    int j = t;
    if (j < DN) {
        float acc = 0.0f;
        if (j == DN - 1) {
            acc = sigm(B[j * DN + (DN - 2)]);
        } else {
            #pragma unroll 4
            for (int k = 0; k < DN; k++) {
                if (k == j) continue;
                acc += sigm(B[j * DN + k]);
            }
        }
        s[j] = acc * inv_n;
    }
    __syncthreads();
    if (j < 2) {
        int i = (DN - 2) + j;
        float acc = 0.0f;
        if (i == DN - 1) {
            acc = sigm(B[i * DN + (DN - 2)]) * (1.0f + s[DN - 2]);
        } else {
            #pragma unroll 4
            for (int k = 0; k < DN; k++) {
                if (k == i) continue;
                acc += sigm(B[i * DN + k]) * (1.0f + s[k]);
            }
        }
        g_c[j] = 1.0f + s[i] + acc * inv_n;
    }
}

// ---------------------------------------------------------------------------
// K2: fused, 512 threads, BT=16 rows/block, cp.async weight pipeline.
// ---------------------------------------------------------------------------
__global__ __launch_bounds__(THREADS) void fused_kernel(
    const float* __restrict__ x,  const float* __restrict__ tt,
    const float* __restrict__ yy, const float* __restrict__ bin,
    const float* __restrict__ bT1, const float* __restrict__ wT2,
    const float* __restrict__ bT2,
    const float* __restrict__ bY1, const float* __restrict__ wY2,
    const float* __restrict__ bY2,
    float* __restrict__ out)
{
    __shared__ __align__(16) float wbuf[3][KC * HID];   // 3 x 8KB
    __shared__ __align__(16) float z_s[BT * ZS];        // [r][k], pads zero
    __shared__ __align__(16) float r0_s[BT * HID];      // [r][hid]
    __shared__ float red_s[2][BT];

    const int t  = threadIdx.x;
    const int b0 = blockIdx.x * BT;

    // stage-A thread map: 4 h-cols x 2 rows
    const int hn = t & 63;          // h = 4*hn
    const int rg = t >> 6;          // rows 2*rg, 2*rg+1   (uniform per warp)
    // stage-B thread map: branch, 4 h-cols x 2 rows
    const int brB = t >> 8;         // 0: T, 1: Y          (uniform per warp)
    const int uB  = t & 255;
    const int hn2 = uB & 31;        // h = 4*hn2
    const int rg2 = uB >> 5;        // rows 2*rg2, 2*rg2+1 (uniform per warp)

    // ---- weight-chunk copy (one cp.async.16 per thread per chunk) ----
    auto issue = [&](int g) {
        float* dstb = wbuf[g % 3];
        if (g < NCA) {
            int kl = t >> 6, hq = t & 63;                       // 8 x 64 float4
            const float* src = g_WinT + (g * KC + kl) * HID + hq * 4;
            cpasync16(dstb + kl * HID + hq * 4, src);
        } else {
            int j = g - NCA;
            int brc = t >> 8, f = t & 255;
            int kl = f >> 5, hq = f & 31;                       // 8 x 32 float4
            const float* W = brc ? g_WY1T : g_WT1T;
            const float* src = W + (j * KC + kl) * MH + hq * 4;
            cpasync16(dstb + brc * (KC * MH) + kl * MH + hq * 4, src);
        }
        asm volatile("cp.async.commit_group;\n" ::: "memory");
    };

    issue(0);
    issue(1);

    // ---- fill z tile [r][k], zero pads (overlaps with cp.async flight) ----
    for (int idx = t; idx < BT * ZS; idx += THREADS) {
        int r = idx / ZS;
        int k = idx - r * ZS;
        int b = b0 + r;
        float v = 0.0f;
        if (k < DX)            v = x[b * DX + k];
        else if (k == DX)      v = tt[b];
        else if (k == DX + 1)  v = yy[b];
        z_s[idx] = v;
    }

    float accA[2][4];
    float accB[2][4];
    #pragma unroll
    for (int i = 0; i < 2; i++)
        #pragma unroll
        for (int j = 0; j < 4; j++) { accA[i][j] = 0.0f; accB[i][j] = 0.0f; }

    for (int g = 0; g < NCH; g++) {
        if (g + 2 < NCH)
            asm volatile("cp.async.wait_group 1;\n" ::: "memory");
        else
            asm volatile("cp.async.wait_group 0;\n" ::: "memory");
        __syncthreads();
        if (g + 2 < NCH) issue(g + 2);

        const float* wb = wbuf[g % 3];

        if (g < NCA) {
            // ---- stage A chunk: k in [g*KC, g*KC+KC) ----
            #pragma unroll
            for (int q = 0; q < KC / 4; q++) {
                const int kg = g * KC + q * 4;
                float4 wv[4];
                #pragma unroll
                for (int kk = 0; kk < 4; kk++)
                    wv[kk] = *(const float4*)(wb + (q * 4 + kk) * HID + 4 * hn);
                #pragma unroll
                for (int rr = 0; rr < 2; rr++) {
                    float4 zv = *(const float4*)(z_s + (2 * rg + rr) * ZS + kg);
                    accA[rr][0] = fmaf(zv.x, wv[0].x, accA[rr][0]);
                    accA[rr][1] = fmaf(zv.x, wv[0].y, accA[rr][1]);
                    accA[rr][2] = fmaf(zv.x, wv[0].z, accA[rr][2]);
                    accA[rr][3] = fmaf(zv.x, wv[0].w, accA[rr][3]);
                    accA[rr][0] = fmaf(zv.y, wv[1].x, accA[rr][0]);
                    accA[rr][1] = fmaf(zv.y, wv[1].y, accA[rr][1]);
                    accA[rr][2] = fmaf(zv.y, wv[1].z, accA[rr][2]);
                    accA[rr][3] = fmaf(zv.y, wv[1].w, accA[rr][3]);
                    accA[rr][0] = fmaf(zv.z, wv[2].x, accA[rr][0]);
                    accA[rr][1] = fmaf(zv.z, wv[2].y, accA[rr][1]);
                    accA[rr][2] = fmaf(zv.z, wv[2].z, accA[rr][2]);
                    accA[rr][3] = fmaf(zv.z, wv[2].w, accA[rr][3]);
                    accA[rr][0] = fmaf(zv.w, wv[3].x, accA[rr][0]);
                    accA[rr][1] = fmaf(zv.w, wv[3].y, accA[rr][1]);
                    accA[rr][2] = fmaf(zv.w, wv[3].z, accA[rr][2]);
                    accA[rr][3] = fmaf(zv.w, wv[3].w, accA[rr][3]);
                }
            }
            if (g == NCA - 1) {
                // stage-A epilogue: bias + relu -> r0_s
                float4 bv = *(const float4*)(bin + 4 * hn);
                #pragma unroll
                for (int rr = 0; rr < 2; rr++) {
                    float4 o;
                    o.x = fmaxf(accA[rr][0] + bv.x, 0.0f);
                    o.y = fmaxf(accA[rr][1] + bv.y, 0.0f);
                    o.z = fmaxf(accA[rr][2] + bv.z, 0.0f);
                    o.w = fmaxf(accA[rr][3] + bv.w, 0.0f);
                    *(float4*)(r0_s + (2 * rg + rr) * HID + 4 * hn) = o;
                }
            }
        } else {
            // ---- stage B chunk: k in [j*KC, j*KC+KC) ----
            const int j = g - NCA;
            const float* wbr = wb + brB * (KC * MH);
            #pragma unroll
            for (int q = 0; q < KC / 4; q++) {
                const int kg = j * KC + q * 4;
                float4 wv[4];
                #pragma unroll
                for (int kk = 0; kk < 4; kk++)
                    wv[kk] = *(const float4*)(wbr + (q * 4 + kk) * MH + 4 * hn2);
                #pragma unroll
                for (int rr = 0; rr < 2; rr++) {
                    float4 zv = *(const float4*)(r0_s + (2 * rg2 + rr) * HID + kg);
                    accB[rr][0] = fmaf(zv.x, wv[0].x, accB[rr][0]);
                    accB[rr][1] = fmaf(zv.x, wv[0].y, accB[rr][1]);
                    accB[rr][2] = fmaf(zv.x, wv[0].z, accB[rr][2]);
                    accB[rr][3] = fmaf(zv.x, wv[0].w, accB[rr][3]);
                    accB[rr][0] = fmaf(zv.y, wv[1].x, accB[rr][0]);
                    accB[rr][1] = fmaf(zv.y, wv[1].y, accB[rr][1]);
                    accB[rr][2] = fmaf(zv.y, wv[1].z, accB[rr][2]);
                    accB[rr][3] = fmaf(zv.y, wv[1].w, accB[rr][3]);
                    accB[rr][0] = fmaf(zv.z, wv[2].x, accB[rr][0]);
                    accB[rr][1] = fmaf(zv.z, wv[2].y, accB[rr][1]);
                    accB[rr][2] = fmaf(zv.z, wv[2].z, accB[rr][2]);
                    accB[rr][3] = fmaf(zv.z, wv[2].w, accB[rr][3]);
                    accB[rr][0] = fmaf(zv.w, wv[3].x, accB[rr][0]);
                    accB[rr][1] = fmaf(zv.w, wv[3].y, accB[rr][1]);
                    accB[rr][2] = fmaf(zv.w, wv[3].z, accB[rr][2]);
                    accB[rr][3] = fmaf(zv.w, wv[3].w, accB[rr][3]);
                }
            }
        }
    }

    // ---- stage-B epilogue: scale, relu, dot w2, warp-reduce over h ----
    {
        const float* b1p = brB ? bY1 : bT1;
        const float* w2p = brB ? wY2 : wT2;
        const float  cs  = g_c[brB];
        float4 b1v = *(const float4*)(b1p + 4 * hn2);
        float4 w2v = *(const float4*)(w2p + 4 * hn2);
        float s[2];
        #pragma unroll
        for (int rr = 0; rr < 2; rr++) {
            float m0 = fmaxf(fmaf(cs, accB[rr][0], b1v.x), 0.0f);
            float m1 = fmaxf(fmaf(cs, accB[rr][1], b1v.y), 0.0f);
            float m2 = fmaxf(fmaf(cs, accB[rr][2], b1v.z), 0.0f);
            float m3 = fmaxf(fmaf(cs, accB[rr][3], b1v.w), 0.0f);
            s[rr] = fmaf(m0, w2v.x, fmaf(m1, w2v.y, fmaf(m2, w2v.z, m3 * w2v.w)));
        }
        #pragma unroll
        for (int off = 16; off > 0; off >>= 1) {
            s[0] += __shfl_xor_sync(0xFFFFFFFFu, s[0], off);
            s[1] += __shfl_xor_sync(0xFFFFFFFFu, s[1], off);
        }
        if (hn2 == 0) {
            red_s[brB][2 * rg2]     = s[0];
            red_s[brB][2 * rg2 + 1] = s[1];
        }
    }
    __syncthreads();

    if (t < BT)
        out[b0 + t] = red_s[0][t] + red_s[1][t] + bT2[0] + bY2[0];
}

// ---------------------------------------------------------------------------
extern "C" void kernel_launch(void* const* d_in, const int* in_sizes, int n_in,
                              void* d_out, int out_size)
{
    const float* x    = (const float*)d_in[0];
    const float* tt   = (const float*)d_in[1];
    const float* yy   = (const float*)d_in[2];
    const float* Bprm = (const float*)d_in[3];
    const float* Win  = (const float*)d_in[4];
    const float* bin  = (const float*)d_in[5];
    const float* WT1  = (const float*)d_in[6];
    const float* bT1  = (const float*)d_in[7];
    const float* wT2  = (const float*)d_in[8];
    const float* bT2  = (const float*)d_in[9];
    const float* WY1  = (const float*)d_in[10];
    const float* bY1  = (const float*)d_in[11];
    const float* wY2  = (const float*)d_in[12];
    const float* bY2  = (const float*)d_in[13];
    float* out = (float*)d_out;

    prep_kernel<<<97, 256>>>(Bprm, Win, WT1, WY1);
    fused_kernel<<<NBLK, THREADS>>>(x, tt, yy, bin,
                                    bT1, wT2, bT2,
                                    bY1, wY2, bY2, out);
}

// round 4
// speedup vs baseline: 2.0523x; 1.0595x over previous
#include <cuda_runtime.h>
#include <cstdint>

// ---------------------------------------------------------------------------
// GNN_EBM reduced form:
//   out[b] = MLP_T(c100 * r0[b]) + MLP_Y(c101 * r0[b]),
//   r0 = relu(z @ Win^T + bin),  z = [x|t|y], c_i from sigmoid(B)*mask rowsums.
//
// Round-4: both GEMM stages on tensor cores via mma.sync m16n8k8 tf32 with
// 3xTF32 error compensation (fp32-grade accuracy). Weights consumed in their
// ORIGINAL [h][k] layout (B operand indexed by (k,n) -> W[n][k]); only Win is
// pad-copied 102->112 by prep (no transpose). cp.async 3-buffer weight
// pipeline; all operand LDS are bank-conflict-free (stride == 20 mod 32).
// ---------------------------------------------------------------------------

#define DX      100
#define DN      102
#define KA      112            // stage-A K padded
#define HID     256
#define MH      128
#define BT      16             // batch rows per block
#define NBLK    128
#define THREADS 512
#define NCA     7              // stage-A chunks (16 k each)
#define NCB     16             // stage-B chunks
#define NCH     (NCA + NCB)    // 23
#define CHS     20             // smem floats per weight row in a chunk (16+4 pad)
#define CHF     (256 * CHS)    // floats per chunk buffer (5120)
#define ZS      116            // z_s row stride (116 % 32 == 20)
#define RS      276            // r0_s row stride (276 % 32 == 20)

#define OFF_Z   (3 * CHF)              // 15360
#define OFF_R0  (OFF_Z + BT * ZS)      // 17216
#define OFF_RED (OFF_R0 + BT * RS)     // 21632
#define SMEM_FLOATS (OFF_RED + 32)     // 21664 floats = 86656 B

__device__ float g_c[2];
__device__ float g_WinP[HID * KA];     // Win rows padded 102 -> 112 (zeros)

__device__ __forceinline__ float sigm(float v) {
    return 1.0f / (1.0f + __expf(-v));
}

__device__ __forceinline__ void cpasync16(void* dst, const void* src) {
    uint32_t d = (uint32_t)__cvta_generic_to_shared(dst);
    asm volatile("cp.async.cg.shared.global [%0], [%1], 16;\n"
                 :: "r"(d), "l"(src) : "memory");
}

__device__ __forceinline__ uint32_t f2tf(float v) {
    uint32_t r;
    asm("cvt.rna.tf32.f32 %0, %1;" : "=r"(r) : "f"(v));
    return r;
}

#define SPLIT(v, hi_, lo_) { hi_ = f2tf(v); lo_ = f2tf((v) - __uint_as_float(hi_)); }

__device__ __forceinline__ void mma8(float* c, const uint32_t* a,
                                     uint32_t b0, uint32_t b1) {
    asm volatile(
        "mma.sync.aligned.m16n8k8.row.col.f32.tf32.tf32.f32 "
        "{%0,%1,%2,%3},{%4,%5,%6,%7},{%8,%9},{%0,%1,%2,%3};"
        : "+f"(c[0]), "+f"(c[1]), "+f"(c[2]), "+f"(c[3])
        : "r"(a[0]), "r"(a[1]), "r"(a[2]), "r"(a[3]), "r"(b0), "r"(b1));
}

// ---------------------------------------------------------------------------
// K1 prep: blocks 0..27 pad-copy Win [256][102] -> g_WinP [256][112];
//          block 28 computes c scalars.
// ---------------------------------------------------------------------------
__global__ __launch_bounds__(256) void prep_kernel(
    const float* __restrict__ B,
    const float* __restrict__ Win)
{
    const int b = blockIdx.x;
    const int t = threadIdx.x;

    if (b < 28) {
        int base = b * 1024;
        #pragma unroll
        for (int i = 0; i < 4; i++) {
            int idx = base + i * 256 + t;       // < 28672 = 256*112
            int h = idx / KA;
            int k = idx - h * KA;
            g_WinP[idx] = (k < DN) ? Win[h * DN + k] : 0.0f;
        }
        return;
    }

    __shared__ float s[DN];
    const float inv_n = 1.0f / (float)DN;
    int j = t;
    if (j < DN) {
        float acc = 0.0f;
        if (j == DN - 1) {
            acc = sigm(B[j * DN + (DN - 2)]);
        } else {
            #pragma unroll 4
            for (int k = 0; k < DN; k++) {
                if (k == j) continue;
                acc += sigm(B[j * DN + k]);
            }
        }
        s[j] = acc * inv_n;
    }
    __syncthreads();
    if (j < 2) {
        int i = (DN - 2) + j;
        float acc = 0.0f;
        if (i == DN - 1) {
            acc = sigm(B[i * DN + (DN - 2)]) * (1.0f + s[DN - 2]);
        } else {
            #pragma unroll 4
            for (int k = 0; k < DN; k++) {
                if (k == i) continue;
                acc += sigm(B[i * DN + k]) * (1.0f + s[k]);
            }
        }
        g_c[j] = 1.0f + s[i] + acc * inv_n;
    }
}

// ---------------------------------------------------------------------------
// K2 fused: 512 threads (16 warps), BT=16 rows/block.
// ---------------------------------------------------------------------------
__global__ __launch_bounds__(THREADS) void fused_kernel(
    const float* __restrict__ x,   const float* __restrict__ tt,
    const float* __restrict__ yy,  const float* __restrict__ bin,
    const float* __restrict__ WT1, const float* __restrict__ bT1,
    const float* __restrict__ wT2, const float* __restrict__ bT2,
    const float* __restrict__ WY1, const float* __restrict__ bY1,
    const float* __restrict__ wY2, const float* __restrict__ bY2,
    float* __restrict__ out)
{
    extern __shared__ __align__(16) float sm[];
    float* ws  = sm;             // 3 chunk buffers, [256][CHS] each
    float* zs  = sm + OFF_Z;     // [16][ZS]
    float* r0s = sm + OFF_R0;    // [16][RS]
    float* red = sm + OFF_RED;   // [2][16]

    const int t    = threadIdx.x;
    const int w    = t >> 5;
    const int lane = t & 31;
    const int grp  = lane >> 2;   // 0..7
    const int qid  = lane & 3;    // 0..3
    const int b0   = blockIdx.x * BT;

    const int brB = w >> 3;       // stage-B branch (0=T, 1=Y)
    const int wb_ = w & 7;        // warp-within-branch

    if (t < 32) red[t] = 0.0f;

    // ---- cp.async weight-chunk issue ----
    auto issue = [&](int g) {
        float* dst = ws + (g % 3) * CHF;
        if (g < NCA) {
            #pragma unroll
            for (int i = 0; i < 2; i++) {
                int seg = t + i * THREADS;          // 1024 segs = 256 rows x 4
                int h = seg >> 2, sub = seg & 3;
                cpasync16(dst + h * CHS + 4 * sub,
                          g_WinP + h * KA + g * 16 + 4 * sub);
            }
        } else {
            int j = g - NCA;
            #pragma unroll
            for (int i = 0; i < 2; i++) {
                int seg = t + i * THREADS;          // 2 br x 128 rows x 4
                int br = seg >> 9, rem = seg & 511;
                int h = rem >> 2, sub = rem & 3;
                const float* W = br ? WY1 : WT1;
                cpasync16(dst + br * (128 * CHS) + h * CHS + 4 * sub,
                          W + h * HID + j * 16 + 4 * sub);
            }
        }
        asm volatile("cp.async.commit_group;\n" ::: "memory");
    };

    issue(0);
    issue(1);

    // ---- fill z tile [r][k] (k >= 102 zero) ----
    for (int idx = t; idx < BT * ZS; idx += THREADS) {
        int r = idx / ZS;
        int k = idx - r * ZS;
        int b = b0 + r;
        float v = 0.0f;
        if (k < DX)            v = x[b * DX + k];
        else if (k == DX)      v = tt[b];
        else if (k == DX + 1)  v = yy[b];
        zs[idx] = v;
    }

    float accA[2][4];
    float accB[2][4];
    #pragma unroll
    for (int i = 0; i < 2; i++)
        #pragma unroll
        for (int j = 0; j < 4; j++) { accA[i][j] = 0.0f; accB[i][j] = 0.0f; }

    // one m16n8k8 k-step: A from act (stride AS, k at kz), B from chunk at kk
    auto kstep = [&](const float* act, int AS, const float* wc, int kk, int kz,
                     int h0a, int h0b, float acc0[4], float acc1[4]) {
        uint32_t ah[4], al[4];
        float av;
        av = act[grp * AS + kz + qid];           SPLIT(av, ah[0], al[0]);
        av = act[(grp + 8) * AS + kz + qid];     SPLIT(av, ah[1], al[1]);
        av = act[grp * AS + kz + qid + 4];       SPLIT(av, ah[2], al[2]);
        av = act[(grp + 8) * AS + kz + qid + 4]; SPLIT(av, ah[3], al[3]);

        const float* bp0 = wc + (h0a + grp) * CHS + kk + qid;
        const float* bp1 = wc + (h0b + grp) * CHS + kk + qid;
        uint32_t bh0, bl0, bh1, bl1;
        float bv0, bv1;

        bv0 = bp0[0]; bv1 = bp0[4];
        SPLIT(bv0, bh0, bl0); SPLIT(bv1, bh1, bl1);
        mma8(acc0, al, bh0, bh1);
        mma8(acc0, ah, bl0, bl1);
        mma8(acc0, ah, bh0, bh1);

        bv0 = bp1[0]; bv1 = bp1[4];
        SPLIT(bv0, bh0, bl0); SPLIT(bv1, bh1, bl1);
        mma8(acc1, al, bh0, bh1);
        mma8(acc1, ah, bl0, bl1);
        mma8(acc1, ah, bh0, bh1);
    };

    for (int g = 0; g < NCH; g++) {
        if (g + 2 < NCH)
            asm volatile("cp.async.wait_group 1;\n" ::: "memory");
        else
            asm volatile("cp.async.wait_group 0;\n" ::: "memory");
        __syncthreads();
        if (g + 2 < NCH) issue(g + 2);

        const float* wc = ws + (g % 3) * CHF;

        if (g < NCA) {
            // stage A: warp's n-tiles at h = 8w and 8w+128
            kstep(zs, ZS, wc, 0, g * 16,     8 * w, 8 * w + 128, accA[0], accA[1]);
            kstep(zs, ZS, wc, 8, g * 16 + 8, 8 * w, 8 * w + 128, accA[0], accA[1]);

            if (g == NCA - 1) {
                // stage-A epilogue: bias + relu -> r0s[r][h]
                #pragma unroll
                for (int t2 = 0; t2 < 2; t2++) {
                    int hc = 8 * w + 128 * t2 + 2 * qid;
                    float bi0 = bin[hc], bi1 = bin[hc + 1];
                    r0s[grp * RS + hc]           = fmaxf(accA[t2][0] + bi0, 0.0f);
                    r0s[grp * RS + hc + 1]       = fmaxf(accA[t2][1] + bi1, 0.0f);
                    r0s[(grp + 8) * RS + hc]     = fmaxf(accA[t2][2] + bi0, 0.0f);
                    r0s[(grp + 8) * RS + hc + 1] = fmaxf(accA[t2][3] + bi1, 0.0f);
                }
            }
        } else {
            // stage B: branch brB, n-tiles at h = 8wb_ and 8wb_+64
            int j = g - NCA;
            const float* wcb = wc + brB * (128 * CHS);
            kstep(r0s, RS, wcb, 0, j * 16,     8 * wb_, 8 * wb_ + 64, accB[0], accB[1]);
            kstep(r0s, RS, wcb, 8, j * 16 + 8, 8 * wb_, 8 * wb_ + 64, accB[0], accB[1]);
        }
    }

    // ---- stage-B epilogue: scale, bias, relu, dot w2, reduce over h ----
    {
        const float* b1p = brB ? bY1 : bT1;
        const float* w2p = brB ? wY2 : wT2;
        const float  cs  = g_c[brB];

        float sl = 0.0f, sh = 0.0f;
        #pragma unroll
        for (int t2 = 0; t2 < 2; t2++) {
            int hc = 8 * wb_ + 64 * t2 + 2 * qid;
            float b10 = b1p[hc], b11 = b1p[hc + 1];
            float w20 = w2p[hc], w21 = w2p[hc + 1];
            float m;
            m = fmaxf(fmaf(cs, accB[t2][0], b10), 0.0f); sl = fmaf(m, w20, sl);
            m = fmaxf(fmaf(cs, accB[t2][1], b11), 0.0f); sl = fmaf(m, w21, sl);
            m = fmaxf(fmaf(cs, accB[t2][2], b10), 0.0f); sh = fmaf(m, w20, sh);
            m = fmaxf(fmaf(cs, accB[t2][3], b11), 0.0f); sh = fmaf(m, w21, sh);
        }
        sl += __shfl_xor_sync(0xFFFFFFFFu, sl, 1);
        sl += __shfl_xor_sync(0xFFFFFFFFu, sl, 2);
        sh += __shfl_xor_sync(0xFFFFFFFFu, sh, 1);
        sh += __shfl_xor_sync(0xFFFFFFFFu, sh, 2);
        if (qid == 0) {
            atomicAdd(&red[brB * 16 + grp], sl);
            atomicAdd(&red[brB * 16 + grp + 8], sh);
        }
    }
    __syncthreads();

    if (t < BT)
        out[b0 + t] = red[t] + red[16 + t] + bT2[0] + bY2[0];
}

// ---------------------------------------------------------------------------
extern "C" void kernel_launch(void* const* d_in, const int* in_sizes, int n_in,
                              void* d_out, int out_size)
{
    const float* x    = (const float*)d_in[0];
    const float* tt   = (const float*)d_in[1];
    const float* yy   = (const float*)d_in[2];
    const float* Bprm = (const float*)d_in[3];
    const float* Win  = (const float*)d_in[4];
    const float* bin  = (const float*)d_in[5];
    const float* WT1  = (const float*)d_in[6];
    const float* bT1  = (const float*)d_in[7];
    const float* wT2  = (const float*)d_in[8];
    const float* bT2  = (const float*)d_in[9];
    const float* WY1  = (const float*)d_in[10];
    const float* bY1  = (const float*)d_in[11];
    const float* wY2  = (const float*)d_in[12];
    const float* bY2  = (const float*)d_in[13];
    float* out = (float*)d_out;

    cudaFuncSetAttribute(fused_kernel,
                         cudaFuncAttributeMaxDynamicSharedMemorySize,
                         SMEM_FLOATS * sizeof(float));

    prep_kernel<<<29, 256>>>(Bprm, Win);
    fused_kernel<<<NBLK, THREADS, SMEM_FLOATS * sizeof(float)>>>(
        x, tt, yy, bin,
        WT1, bT1, wT2, bT2,
        WY1, bY1, wY2, bY2, out);
}

// round 5
// speedup vs baseline: 4.0438x; 1.9704x over previous
#include <cuda_runtime.h>
#include <cstdint>

// ---------------------------------------------------------------------------
// GNN_EBM reduced form:
//   out[b] = MLP_T(c100 * r0[b]) + MLP_Y(c101 * r0[b]),
//   r0 = relu(z @ Win^T + bin),  z = [x|t|y], c_i from sigmoid(B)*mask rowsums.
//
// Round-5:
//  * prep parallelized: 102 blocks do per-row sigmoid sums (s[j]), 28 blocks
//    pad-copy Win. No more single-SM 13K-MUFU serialization.
//  * c0/c1 finalized inside fused kernel prologue (203 sigmoids, overlapped).
//  * activations pre-split to tf32 hi/lo smem arrays (zhi/zlo, r0hi/r0lo);
//    the MMA mainloop has no A-side cvt work.
// ---------------------------------------------------------------------------

#define DX      100
#define DN      102
#define KA      112            // stage-A K padded
#define HID     256
#define MH      128
#define BT      16             // batch rows per block
#define NBLK    128
#define THREADS 512
#define NCA     7              // stage-A chunks (16 k each)
#define NCB     16             // stage-B chunks
#define NCH     (NCA + NCB)    // 23
#define CHS     20             // chunk row stride (16 + 4 pad), 20 mod 32
#define CHF     (256 * CHS)    // floats per chunk buffer (5120)
#define ZS      116            // z row stride (116 % 32 == 20)
#define RS      276            // r0 row stride (276 % 32 == 20)

#define OFF_ZH  (3 * CHF)                 // 15360
#define OFF_ZL  (OFF_ZH + BT * ZS)        // +1856
#define OFF_RH  (OFF_ZL + BT * ZS)
#define OFF_RL  (OFF_RH + BT * RS)        // +4416
#define OFF_RED (OFF_RL + BT * RS)
#define OFF_CC  (OFF_RED + 32)
#define SMEM_FLOATS (OFF_CC + 4)

__device__ float g_c_s[DN];            // s[j] = rowsum_j(A)/N
__device__ float g_WinP[HID * KA];     // Win rows padded 102 -> 112 (zeros)

__device__ __forceinline__ float sigm(float v) {
    return 1.0f / (1.0f + __expf(-v));
}

__device__ __forceinline__ void cpasync16(void* dst, const void* src) {
    uint32_t d = (uint32_t)__cvta_generic_to_shared(dst);
    asm volatile("cp.async.cg.shared.global [%0], [%1], 16;\n"
                 :: "r"(d), "l"(src) : "memory");
}

__device__ __forceinline__ uint32_t f2tf(float v) {
    uint32_t r;
    asm("cvt.rna.tf32.f32 %0, %1;" : "=r"(r) : "f"(v));
    return r;
}

#define SPLIT(v, hi_, lo_) { hi_ = f2tf(v); lo_ = f2tf((v) - __uint_as_float(hi_)); }

__device__ __forceinline__ void mma8(float* c, const uint32_t* a,
                                     uint32_t b0, uint32_t b1) {
    asm volatile(
        "mma.sync.aligned.m16n8k8.row.col.f32.tf32.tf32.f32 "
        "{%0,%1,%2,%3},{%4,%5,%6,%7},{%8,%9},{%0,%1,%2,%3};"
        : "+f"(c[0]), "+f"(c[1]), "+f"(c[2]), "+f"(c[3])
        : "r"(a[0]), "r"(a[1]), "r"(a[2]), "r"(a[3]), "r"(b0), "r"(b1));
}

// ---------------------------------------------------------------------------
// K1 prep (130 blocks x 128 threads):
//   blocks 0..101 : g_c_s[b] = (1/N) * sum_k masked sigm(B[b][k])
//   blocks 102..129: pad-copy Win [256][102] -> g_WinP [256][112]
// ---------------------------------------------------------------------------
__global__ __launch_bounds__(128) void prep_kernel(
    const float* __restrict__ B,
    const float* __restrict__ Win)
{
    const int b = blockIdx.x;
    const int t = threadIdx.x;

    if (b < DN) {
        __shared__ float wsum[4];
        int k = t;
        float v = 0.0f;
        bool valid = (b == DN - 1) ? (k == DN - 2)
                                   : (k < DN && k != b);
        if (valid) v = sigm(B[b * DN + k]);
        #pragma unroll
        for (int off = 16; off > 0; off >>= 1)
            v += __shfl_xor_sync(0xFFFFFFFFu, v, off);
        if ((t & 31) == 0) wsum[t >> 5] = v;
        __syncthreads();
        if (t == 0)
            g_c_s[b] = (wsum[0] + wsum[1] + wsum[2] + wsum[3]) / (float)DN;
        return;
    }

    // pad-copy Win
    int base = (b - DN) * 1024;
    #pragma unroll
    for (int i = 0; i < 8; i++) {
        int idx = base + i * 128 + t;       // < 28672 = 256*112
        int h = idx / KA;
        int k = idx - h * KA;
        g_WinP[idx] = (k < DN) ? Win[h * DN + k] : 0.0f;
    }
}

// ---------------------------------------------------------------------------
// K2 fused: 512 threads (16 warps), BT=16 rows/block.
// ---------------------------------------------------------------------------
__global__ __launch_bounds__(THREADS) void fused_kernel(
    const float* __restrict__ x,   const float* __restrict__ tt,
    const float* __restrict__ yy,  const float* __restrict__ bin,
    const float* __restrict__ WT1, const float* __restrict__ bT1,
    const float* __restrict__ wT2, const float* __restrict__ bT2,
    const float* __restrict__ WY1, const float* __restrict__ bY1,
    const float* __restrict__ wY2, const float* __restrict__ bY2,
    const float* __restrict__ Bp,
    float* __restrict__ out)
{
    extern __shared__ __align__(16) float sm[];
    float* ws   = sm;             // 3 chunk buffers, [256][CHS]
    float* zh   = sm + OFF_ZH;    // [16][ZS] tf32-hi bits of z
    float* zl   = sm + OFF_ZL;    // [16][ZS] tf32-lo bits of z
    float* r0h  = sm + OFF_RH;    // [16][RS]
    float* r0l  = sm + OFF_RL;    // [16][RS]
    float* red  = sm + OFF_RED;   // [2][16]
    float* accc = sm + OFF_CC;    // c partial sums

    const int t    = threadIdx.x;
    const int w    = t >> 5;
    const int lane = t & 31;
    const int grp  = lane >> 2;   // 0..7
    const int qid  = lane & 3;    // 0..3
    const int b0   = blockIdx.x * BT;

    const int brB = w >> 3;       // stage-B branch (0=T, 1=Y)
    const int wb_ = w & 7;        // warp-within-branch

    if (t < 32) red[t] = 0.0f;
    if (t < 4)  accc[t] = 0.0f;
    __syncthreads();

    // ---- cp.async weight-chunk issue ----
    auto issue = [&](int g) {
        float* dst = ws + (g % 3) * CHF;
        if (g < NCA) {
            #pragma unroll
            for (int i = 0; i < 2; i++) {
                int seg = t + i * THREADS;          // 1024 segs = 256 rows x 4
                int h = seg >> 2, sub = seg & 3;
                cpasync16(dst + h * CHS + 4 * sub,
                          g_WinP + h * KA + g * 16 + 4 * sub);
            }
        } else {
            int j = g - NCA;
            #pragma unroll
            for (int i = 0; i < 2; i++) {
                int seg = t + i * THREADS;          // 2 br x 128 rows x 4
                int br = seg >> 9, rem = seg & 511;
                int h = rem >> 2, sub = rem & 3;
                const float* W = br ? WY1 : WT1;
                cpasync16(dst + br * (128 * CHS) + h * CHS + 4 * sub,
                          W + h * HID + j * 16 + 4 * sub);
            }
        }
        asm volatile("cp.async.commit_group;\n" ::: "memory");
    };

    issue(0);
    issue(1);

    // ---- fill z tile split into hi/lo (pads zero) ----
    for (int idx = t; idx < BT * ZS; idx += THREADS) {
        int r = idx / ZS;
        int k = idx - r * ZS;
        int b = b0 + r;
        float v = 0.0f;
        if (k < DX)            v = x[b * DX + k];
        else if (k == DX)      v = tt[b];
        else if (k == DX + 1)  v = yy[b];
        uint32_t hi, lo;
        SPLIT(v, hi, lo);
        zh[idx] = __uint_as_float(hi);
        zl[idx] = __uint_as_float(lo);
    }

    // ---- c partial sums (overlaps pipeline; consumed only in epilogue) ----
    if (t < DN && t != DN - 2) {
        // row 100 contribution (diag j=100 masked)
        atomicAdd(&accc[0], sigm(Bp[(DN - 2) * DN + t]) * (1.0f + g_c_s[t]));
    }
    if (t == 0) {
        // row 101: only col 100 unmasked
        atomicAdd(&accc[1],
                  sigm(Bp[(DN - 1) * DN + (DN - 2)]) * (1.0f + g_c_s[DN - 2]));
    }

    float accA[2][4];
    float accB[2][4];
    #pragma unroll
    for (int i = 0; i < 2; i++)
        #pragma unroll
        for (int j = 0; j < 4; j++) { accA[i][j] = 0.0f; accB[i][j] = 0.0f; }

    // one m16n8k8 k-step: A hi/lo from smem (pre-split), B split in-loop
    auto kstep = [&](const float* ahi, const float* alo, int AS,
                     const float* wc, int kk, int kz,
                     int h0a, int h0b, float acc0[4], float acc1[4]) {
        uint32_t ah[4], al[4];
        ah[0] = __float_as_uint(ahi[grp * AS + kz + qid]);
        ah[1] = __float_as_uint(ahi[(grp + 8) * AS + kz + qid]);
        ah[2] = __float_as_uint(ahi[grp * AS + kz + qid + 4]);
        ah[3] = __float_as_uint(ahi[(grp + 8) * AS + kz + qid + 4]);
        al[0] = __float_as_uint(alo[grp * AS + kz + qid]);
        al[1] = __float_as_uint(alo[(grp + 8) * AS + kz + qid]);
        al[2] = __float_as_uint(alo[grp * AS + kz + qid + 4]);
        al[3] = __float_as_uint(alo[(grp + 8) * AS + kz + qid + 4]);

        const float* bp0 = wc + (h0a + grp) * CHS + kk + qid;
        const float* bp1 = wc + (h0b + grp) * CHS + kk + qid;
        uint32_t bh0, bl0, bh1, bl1;
        float bv0, bv1;

        bv0 = bp0[0]; bv1 = bp0[4];
        SPLIT(bv0, bh0, bl0); SPLIT(bv1, bh1, bl1);
        mma8(acc0, al, bh0, bh1);
        mma8(acc0, ah, bl0, bl1);
        mma8(acc0, ah, bh0, bh1);

        bv0 = bp1[0]; bv1 = bp1[4];
        SPLIT(bv0, bh0, bl0); SPLIT(bv1, bh1, bl1);
        mma8(acc1, al, bh0, bh1);
        mma8(acc1, ah, bl0, bl1);
        mma8(acc1, ah, bh0, bh1);
    };

    for (int g = 0; g < NCH; g++) {
        if (g + 2 < NCH)
            asm volatile("cp.async.wait_group 1;\n" ::: "memory");
        else
            asm volatile("cp.async.wait_group 0;\n" ::: "memory");
        __syncthreads();
        if (g + 2 < NCH) issue(g + 2);

        const float* wc = ws + (g % 3) * CHF;

        if (g < NCA) {
            // stage A: warp's n-tiles at h = 8w and 8w+128
            kstep(zh, zl, ZS, wc, 0, g * 16,     8 * w, 8 * w + 128, accA[0], accA[1]);
            kstep(zh, zl, ZS, wc, 8, g * 16 + 8, 8 * w, 8 * w + 128, accA[0], accA[1]);

            if (g == NCA - 1) {
                // stage-A epilogue: bias + relu, split -> r0h/r0l
                #pragma unroll
                for (int t2 = 0; t2 < 2; t2++) {
                    int hc = 8 * w + 128 * t2 + 2 * qid;
                    float bi0 = bin[hc], bi1 = bin[hc + 1];
                    float v;
                    uint32_t hi, lo;
                    v = fmaxf(accA[t2][0] + bi0, 0.0f); SPLIT(v, hi, lo);
                    r0h[grp * RS + hc] = __uint_as_float(hi);
                    r0l[grp * RS + hc] = __uint_as_float(lo);
                    v = fmaxf(accA[t2][1] + bi1, 0.0f); SPLIT(v, hi, lo);
                    r0h[grp * RS + hc + 1] = __uint_as_float(hi);
                    r0l[grp * RS + hc + 1] = __uint_as_float(lo);
                    v = fmaxf(accA[t2][2] + bi0, 0.0f); SPLIT(v, hi, lo);
                    r0h[(grp + 8) * RS + hc] = __uint_as_float(hi);
                    r0l[(grp + 8) * RS + hc] = __uint_as_float(lo);
                    v = fmaxf(accA[t2][3] + bi1, 0.0f); SPLIT(v, hi, lo);
                    r0h[(grp + 8) * RS + hc + 1] = __uint_as_float(hi);
                    r0l[(grp + 8) * RS + hc + 1] = __uint_as_float(lo);
                }
            }
        } else {
            // stage B: branch brB, n-tiles at h = 8wb_ and 8wb_+64
            int j = g - NCA;
            const float* wcb = wc + brB * (128 * CHS);
            kstep(r0h, r0l, RS, wcb, 0, j * 16,     8 * wb_, 8 * wb_ + 64, accB[0], accB[1]);
            kstep(r0h, r0l, RS, wcb, 8, j * 16 + 8, 8 * wb_, 8 * wb_ + 64, accB[0], accB[1]);
        }
    }

    // ---- stage-B epilogue: c-scale (2x TF32 split would be wrong here: the
    //      scale is applied in fp32 on the accumulator, exactly as reference),
    //      bias, relu, dot w2, reduce over h ----
    {
        const float* b1p = brB ? bY1 : bT1;
        const float* w2p = brB ? wY2 : wT2;
        const float  cs  = 1.0f + g_c_s[DN - 2 + brB] + accc[brB] / (float)DN;

        float sl = 0.0f, sh = 0.0f;
        #pragma unroll
        for (int t2 = 0; t2 < 2; t2++) {
            int hc = 8 * wb_ + 64 * t2 + 2 * qid;
            float b10 = b1p[hc], b11 = b1p[hc + 1];
            float w20 = w2p[hc], w21 = w2p[hc + 1];
            float m;
            m = fmaxf(fmaf(cs, accB[t2][0], b10), 0.0f); sl = fmaf(m, w20, sl);
            m = fmaxf(fmaf(cs, accB[t2][1], b11), 0.0f); sl = fmaf(m, w21, sl);
            m = fmaxf(fmaf(cs, accB[t2][2], b10), 0.0f); sh = fmaf(m, w20, sh);
            m = fmaxf(fmaf(cs, accB[t2][3], b11), 0.0f); sh = fmaf(m, w21, sh);
        }
        sl += __shfl_xor_sync(0xFFFFFFFFu, sl, 1);
        sl += __shfl_xor_sync(0xFFFFFFFFu, sl, 2);
        sh += __shfl_xor_sync(0xFFFFFFFFu, sh, 1);
        sh += __shfl_xor_sync(0xFFFFFFFFu, sh, 2);
        if (qid == 0) {
            atomicAdd(&red[brB * 16 + grp], sl);
            atomicAdd(&red[brB * 16 + grp + 8], sh);
        }
    }
    __syncthreads();

    if (t < BT)
        out[b0 + t] = red[t] + red[16 + t] + bT2[0] + bY2[0];
}

// ---------------------------------------------------------------------------
extern "C" void kernel_launch(void* const* d_in, const int* in_sizes, int n_in,
                              void* d_out, int out_size)
{
    const float* x    = (const float*)d_in[0];
    const float* tt   = (const float*)d_in[1];
    const float* yy   = (const float*)d_in[2];
    const float* Bprm = (const float*)d_in[3];
    const float* Win  = (const float*)d_in[4];
    const float* bin  = (const float*)d_in[5];
    const float* WT1  = (const float*)d_in[6];
    const float* bT1  = (const float*)d_in[7];
    const float* wT2  = (const float*)d_in[8];
    const float* bT2  = (const float*)d_in[9];
    const float* WY1  = (const float*)d_in[10];
    const float* bY1  = (const float*)d_in[11];
    const float* wY2  = (const float*)d_in[12];
    const float* bY2  = (const float*)d_in[13];
    float* out = (float*)d_out;

    cudaFuncSetAttribute(fused_kernel,
                         cudaFuncAttributeMaxDynamicSharedMemorySize,
                         SMEM_FLOATS * sizeof(float));

    prep_kernel<<<130, 128>>>(Bprm, Win);
    fused_kernel<<<NBLK, THREADS, SMEM_FLOATS * sizeof(float)>>>(
        x, tt, yy, bin,
        WT1, bT1, wT2, bT2,
        WY1, bY1, wY2, bY2, Bprm, out);
}

// round 6
// speedup vs baseline: 4.6235x; 1.1434x over previous
#include <cuda_runtime.h>
#include <cstdint>

// ---------------------------------------------------------------------------
// GNN_EBM reduced form:
//   out[b] = MLP_T(c100 * r0[b]) + MLP_Y(c101 * r0[b]),
//   r0 = relu(z @ Win^T + bin),  z = [x|t|y], c_i from sigmoid(B)*mask rowsums.
//
// Round-6: barrier-free mainloop. Each warp streams ITS OWN weight rows
// through a warp-private 4-deep cp.async smem ring (self-paced with
// cp.async.wait_group). Only 2 block barriers total (z fill, A->B handoff).
// TF32 3x-split tensor-core MMAs, activations pre-split hi/lo in smem.
// ---------------------------------------------------------------------------

#define DX      100
#define DN      102
#define KA      112            // stage-A K padded
#define HID     256
#define MH      128
#define BT      16             // batch rows per block
#define NBLK    128
#define THREADS 512
#define NCA     7              // stage-A chunks (16 k each)
#define NCB     16             // stage-B chunks
#define NCH     (NCA + NCB)    // 23
#define CHS     20             // chunk row stride (16 + 4 pad), 20 mod 32
#define WCH     (16 * CHS)     // floats per warp-chunk buffer (320)
#define WRB     (4 * WCH)      // warp ring: 4 chunk buffers (1280 floats)
#define ZS      116            // z row stride  (116 % 32 == 20)
#define RS      276            // r0 row stride (276 % 32 == 20)

#define OFF_ZH  (16 * WRB)                // 20480
#define OFF_ZL  (OFF_ZH + BT * ZS)
#define OFF_RH  (OFF_ZL + BT * ZS)
#define OFF_RL  (OFF_RH + BT * RS)
#define OFF_RED (OFF_RL + BT * RS)
#define OFF_CC  (OFF_RED + 32)
#define SMEM_FLOATS (OFF_CC + 4)          // ~33060 floats = ~129 KB

__device__ float g_c_s[DN];            // s[j] = rowsum_j(A)/N
__device__ float g_WinP[HID * KA];     // Win rows padded 102 -> 112 (zeros)

__device__ __forceinline__ float sigm(float v) {
    return 1.0f / (1.0f + __expf(-v));
}

__device__ __forceinline__ void cpasync16(void* dst, const void* src) {
    uint32_t d = (uint32_t)__cvta_generic_to_shared(dst);
    asm volatile("cp.async.cg.shared.global [%0], [%1], 16;\n"
                 :: "r"(d), "l"(src) : "memory");
}

__device__ __forceinline__ uint32_t f2tf(float v) {
    uint32_t r;
    asm("cvt.rna.tf32.f32 %0, %1;" : "=r"(r) : "f"(v));
    return r;
}

#define SPLIT(v, hi_, lo_) { hi_ = f2tf(v); lo_ = f2tf((v) - __uint_as_float(hi_)); }

__device__ __forceinline__ void mma8(float* c, const uint32_t* a,
                                     uint32_t b0, uint32_t b1) {
    asm volatile(
        "mma.sync.aligned.m16n8k8.row.col.f32.tf32.tf32.f32 "
        "{%0,%1,%2,%3},{%4,%5,%6,%7},{%8,%9},{%0,%1,%2,%3};"
        : "+f"(c[0]), "+f"(c[1]), "+f"(c[2]), "+f"(c[3])
        : "r"(a[0]), "r"(a[1]), "r"(a[2]), "r"(a[3]), "r"(b0), "r"(b1));
}

// ---------------------------------------------------------------------------
// K1 prep (130 blocks x 128 threads):
//   blocks 0..101  : g_c_s[b] = (1/N) * sum_k masked sigm(B[b][k])
//   blocks 102..129: pad-copy Win [256][102] -> g_WinP [256][112]
// ---------------------------------------------------------------------------
__global__ __launch_bounds__(128) void prep_kernel(
    const float* __restrict__ B,
    const float* __restrict__ Win)
{
    const int b = blockIdx.x;
    const int t = threadIdx.x;

    if (b < DN) {
        __shared__ float wsum[4];
        int k = t;
        float v = 0.0f;
        bool valid = (b == DN - 1) ? (k == DN - 2)
                                   : (k < DN && k != b);
        if (valid) v = sigm(B[b * DN + k]);
        #pragma unroll
        for (int off = 16; off > 0; off >>= 1)
            v += __shfl_xor_sync(0xFFFFFFFFu, v, off);
        if ((t & 31) == 0) wsum[t >> 5] = v;
        __syncthreads();
        if (t == 0)
            g_c_s[b] = (wsum[0] + wsum[1] + wsum[2] + wsum[3]) / (float)DN;
        return;
    }

    int base = (b - DN) * 1024;
    #pragma unroll
    for (int i = 0; i < 8; i++) {
        int idx = base + i * 128 + t;       // < 28672 = 256*112
        int h = idx / KA;
        int k = idx - h * KA;
        g_WinP[idx] = (k < DN) ? Win[h * DN + k] : 0.0f;
    }
}

// ---------------------------------------------------------------------------
// K2 fused: 512 threads (16 warps), BT=16 rows/block, barrier-free mainloop.
// ---------------------------------------------------------------------------
__global__ __launch_bounds__(THREADS) void fused_kernel(
    const float* __restrict__ x,   const float* __restrict__ tt,
    const float* __restrict__ yy,  const float* __restrict__ bin,
    const float* __restrict__ WT1, const float* __restrict__ bT1,
    const float* __restrict__ wT2, const float* __restrict__ bT2,
    const float* __restrict__ WY1, const float* __restrict__ bY1,
    const float* __restrict__ wY2, const float* __restrict__ bY2,
    const float* __restrict__ Bp,
    float* __restrict__ out)
{
    extern __shared__ __align__(16) float sm[];
    float* zh   = sm + OFF_ZH;    // [16][ZS] tf32-hi of z
    float* zl   = sm + OFF_ZL;    // [16][ZS] tf32-lo of z
    float* r0h  = sm + OFF_RH;    // [16][RS]
    float* r0l  = sm + OFF_RL;    // [16][RS]
    float* red  = sm + OFF_RED;   // [2][16]
    float* accc = sm + OFF_CC;    // c partial sums

    const int t    = threadIdx.x;
    const int w    = t >> 5;
    const int lane = t & 31;
    const int grp  = lane >> 2;   // 0..7
    const int qid  = lane & 3;    // 0..3
    const int b0   = blockIdx.x * BT;

    const int brB = w >> 3;       // stage-B branch (0=T, 1=Y)
    const int wb_ = w & 7;        // warp-within-branch

    float* wring = sm + w * WRB;  // this warp's private 4-deep ring
    const float* WB1 = brB ? WY1 : WT1;

    if (t < 32) red[t] = 0.0f;
    if (t < 4)  accc[t] = 0.0f;

    // ---- warp-private weight-chunk issue (2 cp.async.16 per lane) ----
    auto issue = [&](int g) {
        float* dst = wring + (g & 3) * WCH;
        #pragma unroll
        for (int i = 0; i < 2; i++) {
            int s = lane + i * 32;            // 0..63
            int row = s >> 2, sub = s & 3;
            const float* src;
            if (g < NCA) {
                int h = (row < 8) ? (8 * w + row) : (8 * w + 120 + row); // +128
                src = g_WinP + h * KA + g * 16 + sub * 4;
            } else {
                int j = g - NCA;
                int h = (row < 8) ? (8 * wb_ + row) : (8 * wb_ + 56 + row); // +64
                src = WB1 + h * HID + j * 16 + sub * 4;
            }
            cpasync16(dst + row * CHS + sub * 4, src);
        }
        asm volatile("cp.async.commit_group;\n" ::: "memory");
    };

    issue(0);
    issue(1);
    issue(2);

    // ---- fill z tile split into hi/lo (pads zero); overlaps cp.async ----
    for (int idx = t; idx < BT * ZS; idx += THREADS) {
        int r = idx / ZS;
        int k = idx - r * ZS;
        int b = b0 + r;
        float v = 0.0f;
        if (k < DX)            v = x[b * DX + k];
        else if (k == DX)      v = tt[b];
        else if (k == DX + 1)  v = yy[b];
        uint32_t hi, lo;
        SPLIT(v, hi, lo);
        zh[idx] = __uint_as_float(hi);
        zl[idx] = __uint_as_float(lo);
    }

    // ---- c partial sums (consumed after the A->B barrier) ----
    if (t < DN && t != DN - 2)
        atomicAdd(&accc[0], sigm(Bp[(DN - 2) * DN + t]) * (1.0f + g_c_s[t]));
    if (t == 0)
        atomicAdd(&accc[1],
                  sigm(Bp[(DN - 1) * DN + (DN - 2)]) * (1.0f + g_c_s[DN - 2]));

    __syncthreads();   // z tile (and red/accc init) visible to all warps

    float accA[2][4];
    float accB[2][4];
    #pragma unroll
    for (int i = 0; i < 2; i++)
        #pragma unroll
        for (int j = 0; j < 4; j++) { accA[i][j] = 0.0f; accB[i][j] = 0.0f; }

    // one m16n8k8 k-step: A hi/lo pre-split in smem; B rows 0..7 / 8..15 of wc
    auto kstep = [&](const float* ahi, const float* alo, int AS,
                     const float* wc, int kk, int kz,
                     float acc0[4], float acc1[4]) {
        uint32_t ah[4], al[4];
        ah[0] = __float_as_uint(ahi[grp * AS + kz + qid]);
        ah[1] = __float_as_uint(ahi[(grp + 8) * AS + kz + qid]);
        ah[2] = __float_as_uint(ahi[grp * AS + kz + qid + 4]);
        ah[3] = __float_as_uint(ahi[(grp + 8) * AS + kz + qid + 4]);
        al[0] = __float_as_uint(alo[grp * AS + kz + qid]);
        al[1] = __float_as_uint(alo[(grp + 8) * AS + kz + qid]);
        al[2] = __float_as_uint(alo[grp * AS + kz + qid + 4]);
        al[3] = __float_as_uint(alo[(grp + 8) * AS + kz + qid + 4]);

        const float* bp0 = wc + grp * CHS + kk + qid;
        const float* bp1 = wc + (8 + grp) * CHS + kk + qid;
        uint32_t bh0, bl0, bh1, bl1;
        float bv0, bv1;

        bv0 = bp0[0]; bv1 = bp0[4];
        SPLIT(bv0, bh0, bl0); SPLIT(bv1, bh1, bl1);
        mma8(acc0, al, bh0, bh1);
        mma8(acc0, ah, bl0, bl1);
        mma8(acc0, ah, bh0, bh1);

        bv0 = bp1[0]; bv1 = bp1[4];
        SPLIT(bv0, bh0, bl0); SPLIT(bv1, bh1, bl1);
        mma8(acc1, al, bh0, bh1);
        mma8(acc1, ah, bl0, bl1);
        mma8(acc1, ah, bh0, bh1);
    };

    // wait so that chunk g's group has completed (groups retire in order)
    auto wait_for = [&](int g) {
        int rem = NCH - 1 - g;   // groups issued after g (pipeline depth 3)
        if (rem >= 2)      asm volatile("cp.async.wait_group 2;\n" ::: "memory");
        else if (rem == 1) asm volatile("cp.async.wait_group 1;\n" ::: "memory");
        else               asm volatile("cp.async.wait_group 0;\n" ::: "memory");
    };

    // ---- stage A: 7 chunks, warp-private pacing ----
    for (int g = 0; g < NCA; g++) {
        wait_for(g);
        if (g + 3 < NCH) issue(g + 3);
        const float* wc = wring + (g & 3) * WCH;
        kstep(zh, zl, ZS, wc, 0, g * 16,     accA[0], accA[1]);
        kstep(zh, zl, ZS, wc, 8, g * 16 + 8, accA[0], accA[1]);
    }

    // stage-A epilogue: bias + relu, split -> r0h/r0l (warp-private cols)
    {
        #pragma unroll
        for (int t2 = 0; t2 < 2; t2++) {
            int hc = 8 * w + 128 * t2 + 2 * qid;
            float bi0 = bin[hc], bi1 = bin[hc + 1];
            float v;
            uint32_t hi, lo;
            v = fmaxf(accA[t2][0] + bi0, 0.0f); SPLIT(v, hi, lo);
            r0h[grp * RS + hc] = __uint_as_float(hi);
            r0l[grp * RS + hc] = __uint_as_float(lo);
            v = fmaxf(accA[t2][1] + bi1, 0.0f); SPLIT(v, hi, lo);
            r0h[grp * RS + hc + 1] = __uint_as_float(hi);
            r0l[grp * RS + hc + 1] = __uint_as_float(lo);
            v = fmaxf(accA[t2][2] + bi0, 0.0f); SPLIT(v, hi, lo);
            r0h[(grp + 8) * RS + hc] = __uint_as_float(hi);
            r0l[(grp + 8) * RS + hc] = __uint_as_float(lo);
            v = fmaxf(accA[t2][3] + bi1, 0.0f); SPLIT(v, hi, lo);
            r0h[(grp + 8) * RS + hc + 1] = __uint_as_float(hi);
            r0l[(grp + 8) * RS + hc + 1] = __uint_as_float(lo);
        }
    }

    __syncthreads();   // r0 handoff (A cols from all warps -> B k-dim)

    // ---- stage B: 16 chunks, warp-private pacing ----
    for (int g = NCA; g < NCH; g++) {
        wait_for(g);
        if (g + 3 < NCH) issue(g + 3);
        const float* wc = wring + (g & 3) * WCH;
        int j = g - NCA;
        kstep(r0h, r0l, RS, wc, 0, j * 16,     accB[0], accB[1]);
        kstep(r0h, r0l, RS, wc, 8, j * 16 + 8, accB[0], accB[1]);
    }

    // ---- stage-B epilogue: c-scale (fp32, as reference), bias, relu,
    //      dot w2, reduce over h ----
    {
        const float* b1p = brB ? bY1 : bT1;
        const float* w2p = brB ? wY2 : wT2;
        const float  cs  = 1.0f + g_c_s[DN - 2 + brB] + accc[brB] / (float)DN;

        float sl = 0.0f, sh = 0.0f;
        #pragma unroll
        for (int t2 = 0; t2 < 2; t2++) {
            int hc = 8 * wb_ + 64 * t2 + 2 * qid;
            float b10 = b1p[hc], b11 = b1p[hc + 1];
            float w20 = w2p[hc], w21 = w2p[hc + 1];
            float m;
            m = fmaxf(fmaf(cs, accB[t2][0], b10), 0.0f); sl = fmaf(m, w20, sl);
            m = fmaxf(fmaf(cs, accB[t2][1], b11), 0.0f); sl = fmaf(m, w21, sl);
            m = fmaxf(fmaf(cs, accB[t2][2], b10), 0.0f); sh = fmaf(m, w20, sh);
            m = fmaxf(fmaf(cs, accB[t2][3], b11), 0.0f); sh = fmaf(m, w21, sh);
        }
        sl += __shfl_xor_sync(0xFFFFFFFFu, sl, 1);
        sl += __shfl_xor_sync(0xFFFFFFFFu, sl, 2);
        sh += __shfl_xor_sync(0xFFFFFFFFu, sh, 1);
        sh += __shfl_xor_sync(0xFFFFFFFFu, sh, 2);
        if (qid == 0) {
            atomicAdd(&red[brB * 16 + grp], sl);
            atomicAdd(&red[brB * 16 + grp + 8], sh);
        }
    }
    __syncthreads();

    if (t < BT)
        out[b0 + t] = red[t] + red[16 + t] + bT2[0] + bY2[0];
}

// ---------------------------------------------------------------------------
extern "C" void kernel_launch(void* const* d_in, const int* in_sizes, int n_in,
                              void* d_out, int out_size)
{
    const float* x    = (const float*)d_in[0];
    const float* tt   = (const float*)d_in[1];
    const float* yy   = (const float*)d_in[2];
    const float* Bprm = (const float*)d_in[3];
    const float* Win  = (const float*)d_in[4];
    const float* bin  = (const float*)d_in[5];
    const float* WT1  = (const float*)d_in[6];
    const float* bT1  = (const float*)d_in[7];
    const float* wT2  = (const float*)d_in[8];
    const float* bT2  = (const float*)d_in[9];
    const float* WY1  = (const float*)d_in[10];
    const float* bY1  = (const float*)d_in[11];
    const float* wY2  = (const float*)d_in[12];
    const float* bY2  = (const float*)d_in[13];
    float* out = (float*)d_out;

    cudaFuncSetAttribute(fused_kernel,
                         cudaFuncAttributeMaxDynamicSharedMemorySize,
                         SMEM_FLOATS * sizeof(float));

    prep_kernel<<<130, 128>>>(Bprm, Win);
    fused_kernel<<<NBLK, THREADS, SMEM_FLOATS * sizeof(float)>>>(
        x, tt, yy, bin,
        WT1, bT1, wT2, bT2,
        WY1, bY1, wY2, bY2, Bprm, out);
}

// round 7
// speedup vs baseline: 5.1654x; 1.1172x over previous
#include <cuda_runtime.h>
#include <cuda_fp16.h>
#include <cstdint>

// ---------------------------------------------------------------------------
// GNN_EBM reduced form:
//   out[b] = MLP_T(c100 * r0[b]) + MLP_Y(c101 * r0[b]),
//   r0 = relu(z @ Win^T + bin),  z = [x|t|y], c_i from sigmoid(B)*mask rowsums.
//
// Round-7: fp16 two-term-split tensor cores (m16n8k16), weights pre-split to
// fp16 hi/lo in prep (zero in-loop cvt), lo-parts scaled by 2^11 to dodge
// fp16 subnormals (separate cross-term accumulator), 1024 threads = 32 warps
// (1 n-tile per warp per stage), warp-private cp.async rings, barrier-free
// mainloop.
// ---------------------------------------------------------------------------

#define DX      100
#define DN      102
#define KA      112            // stage-A K padded
#define HID     256
#define MH      128
#define BT      16             // batch rows per block
#define NBLK    128
#define THREADS 1024
#define NWARP   32
#define NCA     7              // stage-A chunks (16 k each)
#define NCB     16             // stage-B chunks
#define NCH     (NCA + NCB)    // 23
#define LOSC    2048.0f        // lo-part scale (2^11)

// smem geometry (units: 4B words)
#define WCHW    192            // per warp-chunk: 16 half-rows x 12 words
#define WRBW    (4 * WCHW)     // ring of 4 = 768 words per warp
#define ZSW     60             // z row stride in words  (60  % 8 == 4)
#define RSW     132            // r0 row stride in words (132 % 8 == 4)

#define OFF_ZH  (NWARP * WRBW)            // 24576
#define OFF_ZL  (OFF_ZH + BT * ZSW)       // +960
#define OFF_RH  (OFF_ZL + BT * ZSW)
#define OFF_RL  (OFF_RH + BT * RSW)       // +2112
#define OFF_RED (OFF_RL + BT * RSW)
#define OFF_CC  (OFF_RED + 16)
#define SMEM_WORDS (OFF_CC + 4)           // 30740 words = 122960 B

__device__ float  g_c_s[DN];                         // s[j] = rowsum_j(A)/N
__device__ __align__(16) __half g_WinHi[HID * KA];   // [h][k] fp16 hi
__device__ __align__(16) __half g_WinLo[HID * KA];   // [h][k] (v-hi)*2048
__device__ __align__(16) __half g_WBHi[2 * MH * HID];
__device__ __align__(16) __half g_WBLo[2 * MH * HID];

__device__ __forceinline__ float sigm(float v) {
    return 1.0f / (1.0f + __expf(-v));
}

__device__ __forceinline__ void cpasync16(void* dst, const void* src) {
    uint32_t d = (uint32_t)__cvta_generic_to_shared(dst);
    asm volatile("cp.async.cg.shared.global [%0], [%1], 16;\n"
                 :: "r"(d), "l"(src) : "memory");
}

__device__ __forceinline__ void mma16(float* c, const uint32_t* a,
                                      uint32_t b0, uint32_t b1) {
    asm volatile(
        "mma.sync.aligned.m16n8k16.row.col.f32.f16.f16.f32 "
        "{%0,%1,%2,%3},{%4,%5,%6,%7},{%8,%9},{%0,%1,%2,%3};"
        : "+f"(c[0]), "+f"(c[1]), "+f"(c[2]), "+f"(c[3])
        : "r"(a[0]), "r"(a[1]), "r"(a[2]), "r"(a[3]), "r"(b0), "r"(b1));
}

__device__ __forceinline__ uint32_t pack_split(float v, __half* lo_out) {
    __half hi = __float2half_rn(v);
    __half lo = __float2half_rn((v - __half2float(hi)) * LOSC);
    *lo_out = lo;
    return (uint32_t)__half_as_ushort(hi);
}

// ---------------------------------------------------------------------------
// K1 prep (194 blocks x 128 threads):
//   blocks 0..101  : g_c_s[b]
//   blocks 102..129: split Win  -> g_WinHi/Lo  [256][112] (pad zero)
//   blocks 130..193: split WT1/WY1 -> g_WBHi/Lo [2][128][256]
// ---------------------------------------------------------------------------
__global__ __launch_bounds__(128) void prep_kernel(
    const float* __restrict__ B,   const float* __restrict__ Win,
    const float* __restrict__ WT1, const float* __restrict__ WY1)
{
    const int b = blockIdx.x;
    const int t = threadIdx.x;

    if (b < DN) {
        __shared__ float wsum[4];
        int k = t;
        float v = 0.0f;
        bool valid = (b == DN - 1) ? (k == DN - 2) : (k < DN && k != b);
        if (valid) v = sigm(B[b * DN + k]);
        #pragma unroll
        for (int off = 16; off > 0; off >>= 1)
            v += __shfl_xor_sync(0xFFFFFFFFu, v, off);
        if ((t & 31) == 0) wsum[t >> 5] = v;
        __syncthreads();
        if (t == 0)
            g_c_s[b] = (wsum[0] + wsum[1] + wsum[2] + wsum[3]) / (float)DN;
        return;
    }

    if (b < DN + 28) {
        int base = (b - DN) * 1024;
        #pragma unroll
        for (int i = 0; i < 8; i++) {
            int idx = base + i * 128 + t;          // < 28672 = 256*112
            int h = idx / KA, k = idx - h * KA;
            float v = (k < DN) ? Win[h * DN + k] : 0.0f;
            __half hi = __float2half_rn(v);
            g_WinHi[idx] = hi;
            g_WinLo[idx] = __float2half_rn((v - __half2float(hi)) * LOSC);
        }
        return;
    }

    int base = (b - DN - 28) * 1024;
    #pragma unroll
    for (int i = 0; i < 8; i++) {
        int idx = base + i * 128 + t;              // < 65536 = 2*128*256
        int br = idx >> 15, rem = idx & 32767;
        float v = br ? WY1[rem] : WT1[rem];
        __half hi = __float2half_rn(v);
        g_WBHi[idx] = hi;
        g_WBLo[idx] = __float2half_rn((v - __half2float(hi)) * LOSC);
    }
}

// ---------------------------------------------------------------------------
// K2 fused: 1024 threads (32 warps), BT=16 rows/block.
// Warp w: stage A n-tile = cols [8w, 8w+8); stage B: branch w>>4, cols 8*(w&15).
// ---------------------------------------------------------------------------
__global__ __launch_bounds__(THREADS, 1) void fused_kernel(
    const float* __restrict__ x,   const float* __restrict__ tt,
    const float* __restrict__ yy,  const float* __restrict__ bin,
    const float* __restrict__ bT1, const float* __restrict__ wT2,
    const float* __restrict__ bT2,
    const float* __restrict__ bY1, const float* __restrict__ wY2,
    const float* __restrict__ bY2,
    const float* __restrict__ Bp,
    float* __restrict__ out)
{
    extern __shared__ __align__(16) uint32_t smw[];
    uint32_t* zh  = smw + OFF_ZH;    // [16][ZSW]  fp16-hi pairs of z
    uint32_t* zl  = smw + OFF_ZL;    // lo*2048
    uint32_t* r0h = smw + OFF_RH;    // [16][RSW]
    uint32_t* r0l = smw + OFF_RL;
    float*    red  = (float*)(smw + OFF_RED);   // [16]
    float*    accc = (float*)(smw + OFF_CC);

    const int t    = threadIdx.x;
    const int w    = t >> 5;
    const int lane = t & 31;
    const int grp  = lane >> 2;   // 0..7
    const int qid  = lane & 3;    // 0..3
    const int b0   = blockIdx.x * BT;

    const int brB = w >> 4;       // stage-B branch (0=T, 1=Y)
    const int wb_ = w & 15;

    uint32_t* ring = smw + w * WRBW;   // warp-private 4-deep ring

    if (t < 16) red[t] = 0.0f;
    if (t < 4)  accc[t & 1] = 0.0f;    // accc[0], accc[1]

    // ---- warp-private weight-chunk issue: 1 cp.async.16 per lane ----
    auto issue = [&](int g) {
        uint32_t* dst = ring + (g & 3) * WCHW;
        int part = lane >> 4;            // 0 hi, 1 lo
        int r    = (lane >> 1) & 7;      // weight row within tile
        int sgm  = lane & 1;             // 16B segment within row
        const __half* src;
        if (g < NCA) {
            const __half* base = part ? g_WinLo : g_WinHi;
            src = base + (8 * w + r) * KA + g * 16 + sgm * 8;
        } else {
            int j = g - NCA;
            const __half* base = part ? g_WBLo : g_WBHi;
            src = base + brB * (MH * HID) + (8 * wb_ + r) * HID + j * 16 + sgm * 8;
        }
        cpasync16(dst + (part * 8 + r) * 12 + sgm * 4, src);
        asm volatile("cp.async.commit_group;\n" ::: "memory");
    };

    issue(0);
    issue(1);
    issue(2);

    // ---- fill z tile as fp16 hi/lo pairs (pads zero) ----
    // each word = 2 halves (k even, k odd); 16 rows x ZSW words
    for (int idx = t; idx < BT * ZSW; idx += THREADS) {
        int r  = idx / ZSW;
        int kw = idx - r * ZSW;          // word -> k = 2*kw, 2*kw+1
        int b  = b0 + r;
        float v0 = 0.0f, v1 = 0.0f;
        int k0 = 2 * kw;
        if (k0 < DX)            v0 = x[b * DX + k0];
        else if (k0 == DX)      v0 = tt[b];
        else if (k0 == DX + 1)  v0 = yy[b];
        int k1 = k0 + 1;
        if (k1 < DX)            v1 = x[b * DX + k1];
        else if (k1 == DX)      v1 = tt[b];
        else if (k1 == DX + 1)  v1 = yy[b];
        __half l0, l1;
        uint32_t h0 = pack_split(v0, &l0);
        uint32_t h1 = pack_split(v1, &l1);
        zh[idx] = h0 | (h1 << 16);
        zl[idx] = (uint32_t)__half_as_ushort(l0)
                | ((uint32_t)__half_as_ushort(l1) << 16);
    }
    __syncthreads();   // z visible; red/accc init visible

    // ---- c partial sums (consumed after the A->B barrier) ----
    if (t < DN && t != DN - 2)
        atomicAdd(&accc[0], sigm(Bp[(DN - 2) * DN + t]) * (1.0f + g_c_s[t]));
    if (t == 0)
        atomicAdd(&accc[1],
                  sigm(Bp[(DN - 1) * DN + (DN - 2)]) * (1.0f + g_c_s[DN - 2]));

    float accM[4], accX[4];
    #pragma unroll
    for (int i = 0; i < 4; i++) { accM[i] = 0.0f; accX[i] = 0.0f; }

    // one 16-k chunk: main (hi*hi) into accM, cross (hi*lo + lo*hi) into accX
    auto dochunk = [&](const uint32_t* ahArr, const uint32_t* alArr, int AS,
                       int kw, const uint32_t* wc) {
        uint32_t ah[4], al[4];
        ah[0] = ahArr[grp * AS + kw + qid];
        ah[1] = ahArr[(grp + 8) * AS + kw + qid];
        ah[2] = ahArr[grp * AS + kw + qid + 4];
        ah[3] = ahArr[(grp + 8) * AS + kw + qid + 4];
        al[0] = alArr[grp * AS + kw + qid];
        al[1] = alArr[(grp + 8) * AS + kw + qid];
        al[2] = alArr[grp * AS + kw + qid + 4];
        al[3] = alArr[(grp + 8) * AS + kw + qid + 4];

        uint32_t bh0 = wc[grp * 12 + qid];
        uint32_t bh1 = wc[grp * 12 + qid + 4];
        uint32_t bl0 = wc[96 + grp * 12 + qid];
        uint32_t bl1 = wc[96 + grp * 12 + qid + 4];

        mma16(accM, ah, bh0, bh1);
        mma16(accX, ah, bl0, bl1);
        mma16(accX, al, bh0, bh1);
    };

    auto wait_for = [&](int g) {
        int rem = NCH - 1 - g;
        if (rem >= 2)      asm volatile("cp.async.wait_group 2;\n" ::: "memory");
        else if (rem == 1) asm volatile("cp.async.wait_group 1;\n" ::: "memory");
        else               asm volatile("cp.async.wait_group 0;\n" ::: "memory");
    };

    // ---- stage A: 7 chunks ----
    for (int g = 0; g < NCA; g++) {
        wait_for(g);
        if (g + 3 < NCH) issue(g + 3);
        dochunk(zh, zl, ZSW, g * 8, ring + (g & 3) * WCHW);
    }

    // stage-A epilogue: combine, bias, relu, re-split -> r0h/r0l
    {
        const float inv = 1.0f / LOSC;
        int h0 = 8 * w + 2 * qid;
        float bi0 = bin[h0], bi1 = bin[h0 + 1];
        float v00 = fmaxf(fmaf(accX[0], inv, accM[0]) + bi0, 0.0f); // row grp,   col h0
        float v01 = fmaxf(fmaf(accX[1], inv, accM[1]) + bi1, 0.0f); // row grp,   col h0+1
        float v10 = fmaxf(fmaf(accX[2], inv, accM[2]) + bi0, 0.0f); // row grp+8, col h0
        float v11 = fmaxf(fmaf(accX[3], inv, accM[3]) + bi1, 0.0f);
        __half l0, l1;
        uint32_t a, bq;
        int wofs = 4 * w + qid;           // word col = h0/2
        a = pack_split(v00, &l0); bq = pack_split(v01, &l1);
        r0h[grp * RSW + wofs] = a | (bq << 16);
        r0l[grp * RSW + wofs] = (uint32_t)__half_as_ushort(l0)
                              | ((uint32_t)__half_as_ushort(l1) << 16);
        a = pack_split(v10, &l0); bq = pack_split(v11, &l1);
        r0h[(grp + 8) * RSW + wofs] = a | (bq << 16);
        r0l[(grp + 8) * RSW + wofs] = (uint32_t)__half_as_ushort(l0)
                                    | ((uint32_t)__half_as_ushort(l1) << 16);
    }

    __syncthreads();   // r0 handoff

    #pragma unroll
    for (int i = 0; i < 4; i++) { accM[i] = 0.0f; accX[i] = 0.0f; }

    // ---- stage B: 16 chunks ----
    for (int g = NCA; g < NCH; g++) {
        wait_for(g);
        if (g + 3 < NCH) issue(g + 3);
        dochunk(r0h, r0l, RSW, (g - NCA) * 8, ring + (g & 3) * WCHW);
    }

    // ---- stage-B epilogue: c-scale, bias, relu, dot w2, reduce ----
    {
        const float inv = 1.0f / LOSC;
        const float* b1p = brB ? bY1 : bT1;
        const float* w2p = brB ? wY2 : wT2;
        const float  cs  = 1.0f + g_c_s[DN - 2 + brB] + accc[brB] / (float)DN;

        int h0 = 8 * wb_ + 2 * qid;
        float b10 = b1p[h0], b11 = b1p[h0 + 1];
        float w20 = w2p[h0], w21 = w2p[h0 + 1];
        float m, sl = 0.0f, sh = 0.0f;
        m = fmaxf(fmaf(cs, fmaf(accX[0], inv, accM[0]), b10), 0.0f); sl = fmaf(m, w20, sl);
        m = fmaxf(fmaf(cs, fmaf(accX[1], inv, accM[1]), b11), 0.0f); sl = fmaf(m, w21, sl);
        m = fmaxf(fmaf(cs, fmaf(accX[2], inv, accM[2]), b10), 0.0f); sh = fmaf(m, w20, sh);
        m = fmaxf(fmaf(cs, fmaf(accX[3], inv, accM[3]), b11), 0.0f); sh = fmaf(m, w21, sh);
        sl += __shfl_xor_sync(0xFFFFFFFFu, sl, 1);
        sl += __shfl_xor_sync(0xFFFFFFFFu, sl, 2);
        sh += __shfl_xor_sync(0xFFFFFFFFu, sh, 1);
        sh += __shfl_xor_sync(0xFFFFFFFFu, sh, 2);
        if (qid == 0) {
            atomicAdd(&red[grp], sl);
            atomicAdd(&red[grp + 8], sh);
        }
    }
    __syncthreads();

    if (t < BT)
        out[b0 + t] = red[t] + bT2[0] + bY2[0];
}

// ---------------------------------------------------------------------------
extern "C" void kernel_launch(void* const* d_in, const int* in_sizes, int n_in,
                              void* d_out, int out_size)
{
    const float* x    = (const float*)d_in[0];
    const float* tt   = (const float*)d_in[1];
    const float* yy   = (const float*)d_in[2];
    const float* Bprm = (const float*)d_in[3];
    const float* Win  = (const float*)d_in[4];
    const float* bin  = (const float*)d_in[5];
    const float* WT1  = (const float*)d_in[6];
    const float* bT1  = (const float*)d_in[7];
    const float* wT2  = (const float*)d_in[8];
    const float* bT2  = (const float*)d_in[9];
    const float* WY1  = (const float*)d_in[10];
    const float* bY1  = (const float*)d_in[11];
    const float* wY2  = (const float*)d_in[12];
    const float* bY2  = (const float*)d_in[13];
    float* out = (float*)d_out;

    cudaFuncSetAttribute(fused_kernel,
                         cudaFuncAttributeMaxDynamicSharedMemorySize,
                         SMEM_WORDS * sizeof(uint32_t));

    prep_kernel<<<194, 128>>>(Bprm, Win, WT1, WY1);
    fused_kernel<<<NBLK, THREADS, SMEM_WORDS * sizeof(uint32_t)>>>(
        x, tt, yy, bin,
        bT1, wT2, bT2,
        bY1, wY2, bY2, Bprm, out);
}

// round 8
// speedup vs baseline: 6.6227x; 1.2821x over previous
#include <cuda_runtime.h>
#include <cuda_fp16.h>
#include <cstdint>

// ---------------------------------------------------------------------------
// GNN_EBM reduced form:
//   out[b] = MLP_T(c100 * r0[b]) + MLP_Y(c101 * r0[b]),
//   r0 = relu(z @ Win^T + bin),  z = [x|t|y], c_i from sigmoid(B)*mask rowsums.
//
// Round-8: weights pre-packed by prep into per-(tile,chunk,lane) MMA fragment
// uint4s {bh0,bh1,bl0,bl1} (fp16 two-term split, lo scaled 2^11). Mainloop per
// 16-k chunk: 1 coalesced LDG.128 + 2 ldmatrix.x4 (A hi/lo) + 3 m16n8k16 MMAs.
// No cp.async, no rings, 25KB smem, 32 warps.
// ---------------------------------------------------------------------------

#define DX      100
#define DN      102
#define HID     256
#define MH      128
#define BT      16             // batch rows per block
#define NBLK    128
#define THREADS 1024
#define NCA     7              // stage-A chunks (16 k each)
#define NCB     16             // stage-B chunks
#define LOSC    2048.0f        // lo-part scale (2^11)

#define ZSW     60             // z row stride in 4B words  (>= 56, mult of 4)
#define RSW     132            // r0 row stride in words (>= 128, mult of 4)

__device__ float g_c_s[DN];                        // s[j] = rowsum_j(A)/N
__device__ __align__(16) uint4 g_fA[32 * NCA * 32];   // [tile][chunk][lane]
__device__ __align__(16) uint4 g_fB[32 * NCB * 32];   // [br*16+wb][chunk][lane]

__device__ __forceinline__ float sigm(float v) {
    return 1.0f / (1.0f + __expf(-v));
}

__device__ __forceinline__ void mma16(float* c, const uint32_t* a,
                                      uint32_t b0, uint32_t b1) {
    asm volatile(
        "mma.sync.aligned.m16n8k16.row.col.f32.f16.f16.f32 "
        "{%0,%1,%2,%3},{%4,%5,%6,%7},{%8,%9},{%0,%1,%2,%3};"
        : "+f"(c[0]), "+f"(c[1]), "+f"(c[2]), "+f"(c[3])
        : "r"(a[0]), "r"(a[1]), "r"(a[2]), "r"(a[3]), "r"(b0), "r"(b1));
}

__device__ __forceinline__ void ldsm4(uint32_t* r, uint32_t saddr) {
    asm volatile(
        "ldmatrix.sync.aligned.m8n8.x4.shared.b16 {%0,%1,%2,%3}, [%4];"
        : "=r"(r[0]), "=r"(r[1]), "=r"(r[2]), "=r"(r[3]) : "r"(saddr));
}

__device__ __forceinline__ uint32_t smem_u32(const void* p) {
    return (uint32_t)__cvta_generic_to_shared(p);
}

__device__ __forceinline__ uint32_t pack_hi2(float v0, float v1) {
    __half h0 = __float2half_rn(v0), h1 = __float2half_rn(v1);
    return (uint32_t)__half_as_ushort(h0)
         | ((uint32_t)__half_as_ushort(h1) << 16);
}
__device__ __forceinline__ uint32_t pack_lo2(float v0, float v1) {
    __half h0 = __float2half_rn(v0), h1 = __float2half_rn(v1);
    float l0 = (v0 - __half2float(h0)) * LOSC;
    float l1 = (v1 - __half2float(h1)) * LOSC;
    __half a = __float2half_rn(l0), b = __float2half_rn(l1);
    return (uint32_t)__half_as_ushort(a)
         | ((uint32_t)__half_as_ushort(b) << 16);
}

// ---------------------------------------------------------------------------
// K1 prep (286 blocks x 128 threads):
//   blocks 0..101 : g_c_s[b]
//   blocks 102..  : build fragment-packed weights g_fA (7168 u4), g_fB (16384)
// ---------------------------------------------------------------------------
__global__ __launch_bounds__(128) void prep_kernel(
    const float* __restrict__ B,   const float* __restrict__ Win,
    const float* __restrict__ WT1, const float* __restrict__ WY1)
{
    const int b = blockIdx.x;
    const int t = threadIdx.x;

    if (b < DN) {
        __shared__ float wsum[4];
        int k = t;
        float v = 0.0f;
        bool valid = (b == DN - 1) ? (k == DN - 2) : (k < DN && k != b);
        if (valid) v = sigm(B[b * DN + k]);
        #pragma unroll
        for (int off = 16; off > 0; off >>= 1)
            v += __shfl_xor_sync(0xFFFFFFFFu, v, off);
        if ((t & 31) == 0) wsum[t >> 5] = v;
        __syncthreads();
        if (t == 0)
            g_c_s[b] = (wsum[0] + wsum[1] + wsum[2] + wsum[3]) / (float)DN;
        return;
    }

    int fid = (b - DN) * 128 + t;       // fragment uint4 index
    if (fid < 32 * NCA * 32) {
        // stage A: tile nt (8 h-rows), chunk g, lane
        int nt   = fid / (NCA * 32);
        int rem  = fid - nt * (NCA * 32);
        int g    = rem >> 5;
        int lane = rem & 31;
        int h  = 8 * nt + (lane >> 2);
        int k0 = 16 * g + 2 * (lane & 3);
        const float* wr = Win + h * DN;
        float v0 = (k0     < DN) ? wr[k0]     : 0.0f;
        float v1 = (k0 + 1 < DN) ? wr[k0 + 1] : 0.0f;
        float v2 = (k0 + 8 < DN) ? wr[k0 + 8] : 0.0f;
        float v3 = (k0 + 9 < DN) ? wr[k0 + 9] : 0.0f;
        uint4 o;
        o.x = pack_hi2(v0, v1);
        o.y = pack_hi2(v2, v3);
        o.z = pack_lo2(v0, v1);
        o.w = pack_lo2(v2, v3);
        g_fA[fid] = o;
        return;
    }

    int fid2 = fid - 32 * NCA * 32;
    if (fid2 < 32 * NCB * 32) {
        int tile = fid2 / (NCB * 32);   // br*16 + wb
        int rem  = fid2 - tile * (NCB * 32);
        int j    = rem >> 5;
        int lane = rem & 31;
        const float* W = (tile >> 4) ? WY1 : WT1;
        int h  = 8 * (tile & 15) + (lane >> 2);
        int k0 = 16 * j + 2 * (lane & 3);
        const float* wr = W + h * HID;
        float v0 = wr[k0], v1 = wr[k0 + 1], v2 = wr[k0 + 8], v3 = wr[k0 + 9];
        uint4 o;
        o.x = pack_hi2(v0, v1);
        o.y = pack_hi2(v2, v3);
        o.z = pack_lo2(v0, v1);
        o.w = pack_lo2(v2, v3);
        g_fB[fid2] = o;
    }
}

// ---------------------------------------------------------------------------
// K2 fused: 1024 threads (32 warps), BT=16 rows/block.
// Warp w: stage A n-tile = cols [8w, 8w+8); stage B: branch w>>4, cols 8*(w&15).
// ---------------------------------------------------------------------------
__global__ __launch_bounds__(THREADS, 1) void fused_kernel(
    const float* __restrict__ x,   const float* __restrict__ tt,
    const float* __restrict__ yy,  const float* __restrict__ bin,
    const float* __restrict__ bT1, const float* __restrict__ wT2,
    const float* __restrict__ bT2,
    const float* __restrict__ bY1, const float* __restrict__ wY2,
    const float* __restrict__ bY2,
    const float* __restrict__ Bp,
    float* __restrict__ out)
{
    __shared__ __align__(16) uint32_t zh[BT * ZSW];
    __shared__ __align__(16) uint32_t zl[BT * ZSW];
    __shared__ __align__(16) uint32_t r0h[BT * RSW];
    __shared__ __align__(16) uint32_t r0l[BT * RSW];
    __shared__ float red[16];
    __shared__ float accc[2];

    const int t    = threadIdx.x;
    const int w    = t >> 5;
    const int lane = t & 31;
    const int grp  = lane >> 2;
    const int qid  = lane & 3;
    const int b0   = blockIdx.x * BT;

    const int brB = w >> 4;       // stage-B branch (0=T, 1=Y)
    const int wb_ = w & 15;

    if (t < 16) red[t] = 0.0f;
    if (t < 2)  accc[t] = 0.0f;

    // ---- fill z tile as fp16 hi/lo word pairs (pads zero) ----
    for (int idx = t; idx < BT * ZSW; idx += THREADS) {
        int r  = idx / ZSW;
        int kw = idx - r * ZSW;
        int b  = b0 + r;
        float v0 = 0.0f, v1 = 0.0f;
        int k0 = 2 * kw;
        if (k0 < DX)            v0 = x[b * DX + k0];
        else if (k0 == DX)      v0 = tt[b];
        else if (k0 == DX + 1)  v0 = yy[b];
        int k1 = k0 + 1;
        if (k1 < DX)            v1 = x[b * DX + k1];
        else if (k1 == DX)      v1 = tt[b];
        else if (k1 == DX + 1)  v1 = yy[b];
        zh[idx] = pack_hi2(v0, v1);
        zl[idx] = pack_lo2(v0, v1);
    }
    __syncthreads();

    // ---- c partial sums (consumed after the A->B barrier) ----
    if (t < DN && t != DN - 2)
        atomicAdd(&accc[0], sigm(Bp[(DN - 2) * DN + t]) * (1.0f + g_c_s[t]));
    if (t == 0)
        atomicAdd(&accc[1],
                  sigm(Bp[(DN - 1) * DN + (DN - 2)]) * (1.0f + g_c_s[DN - 2]));

    // ldmatrix per-lane source addresses (byte offsets into smem rows)
    const int arow = lane & 15;
    const int acol = (lane >> 4) * 4;   // word offset within row
    const uint32_t zh_a  = smem_u32(zh)  + (arow * ZSW + acol) * 4;
    const uint32_t zl_a  = smem_u32(zl)  + (arow * ZSW + acol) * 4;
    const uint32_t r0h_a = smem_u32(r0h) + (arow * RSW + acol) * 4;
    const uint32_t r0l_a = smem_u32(r0l) + (arow * RSW + acol) * 4;

    float accM[4], accX[4];
    #pragma unroll
    for (int i = 0; i < 4; i++) { accM[i] = 0.0f; accX[i] = 0.0f; }

    // ---- stage A: 7 chunks, fully unrolled ----
    const uint4* fA = g_fA + (w * NCA) * 32 + lane;
    #pragma unroll
    for (int g = 0; g < NCA; g++) {
        uint4 wv = __ldg(fA + g * 32);
        uint32_t ah[4], al[4];
        ldsm4(ah, zh_a + g * 32);       // 8 words = 32B per chunk step
        ldsm4(al, zl_a + g * 32);
        mma16(accM, ah, wv.x, wv.y);
        mma16(accX, ah, wv.z, wv.w);
        mma16(accX, al, wv.x, wv.y);
    }

    // stage-A epilogue: combine, bias, relu, re-split -> r0h/r0l
    {
        const float inv = 1.0f / LOSC;
        int h0 = 8 * w + 2 * qid;
        float bi0 = bin[h0], bi1 = bin[h0 + 1];
        float v00 = fmaxf(fmaf(accX[0], inv, accM[0]) + bi0, 0.0f);
        float v01 = fmaxf(fmaf(accX[1], inv, accM[1]) + bi1, 0.0f);
        float v10 = fmaxf(fmaf(accX[2], inv, accM[2]) + bi0, 0.0f);
        float v11 = fmaxf(fmaf(accX[3], inv, accM[3]) + bi1, 0.0f);
        int wofs = 4 * w + qid;         // word col = h0/2
        r0h[grp * RSW + wofs]       = pack_hi2(v00, v01);
        r0l[grp * RSW + wofs]       = pack_lo2(v00, v01);
        r0h[(grp + 8) * RSW + wofs] = pack_hi2(v10, v11);
        r0l[(grp + 8) * RSW + wofs] = pack_lo2(v10, v11);
    }

    __syncthreads();   // r0 handoff

    #pragma unroll
    for (int i = 0; i < 4; i++) { accM[i] = 0.0f; accX[i] = 0.0f; }

    // ---- stage B: 16 chunks ----
    const uint4* fB = g_fB + ((brB * 16 + wb_) * NCB) * 32 + lane;
    #pragma unroll 8
    for (int j = 0; j < NCB; j++) {
        uint4 wv = __ldg(fB + j * 32);
        uint32_t ah[4], al[4];
        ldsm4(ah, r0h_a + j * 32);
        ldsm4(al, r0l_a + j * 32);
        mma16(accM, ah, wv.x, wv.y);
        mma16(accX, ah, wv.z, wv.w);
        mma16(accX, al, wv.x, wv.y);
    }

    // ---- stage-B epilogue: c-scale, bias, relu, dot w2, reduce ----
    {
        const float inv = 1.0f / LOSC;
        const float* b1p = brB ? bY1 : bT1;
        const float* w2p = brB ? wY2 : wT2;
        const float  cs  = 1.0f + g_c_s[DN - 2 + brB] + accc[brB] / (float)DN;

        int h0 = 8 * wb_ + 2 * qid;
        float b10 = b1p[h0], b11 = b1p[h0 + 1];
        float w20 = w2p[h0], w21 = w2p[h0 + 1];
        float m, sl = 0.0f, sh = 0.0f;
        m = fmaxf(fmaf(cs, fmaf(accX[0], inv, accM[0]), b10), 0.0f); sl = fmaf(m, w20, sl);
        m = fmaxf(fmaf(cs, fmaf(accX[1], inv, accM[1]), b11), 0.0f); sl = fmaf(m, w21, sl);
        m = fmaxf(fmaf(cs, fmaf(accX[2], inv, accM[2]), b10), 0.0f); sh = fmaf(m, w20, sh);
        m = fmaxf(fmaf(cs, fmaf(accX[3], inv, accM[3]), b11), 0.0f); sh = fmaf(m, w21, sh);
        sl += __shfl_xor_sync(0xFFFFFFFFu, sl, 1);
        sl += __shfl_xor_sync(0xFFFFFFFFu, sl, 2);
        sh += __shfl_xor_sync(0xFFFFFFFFu, sh, 1);
        sh += __shfl_xor_sync(0xFFFFFFFFu, sh, 2);
        if (qid == 0) {
            atomicAdd(&red[grp], sl);
            atomicAdd(&red[grp + 8], sh);
        }
    }
    __syncthreads();

    if (t < BT)
        out[b0 + t] = red[t] + bT2[0] + bY2[0];
}

// ---------------------------------------------------------------------------
extern "C" void kernel_launch(void* const* d_in, const int* in_sizes, int n_in,
                              void* d_out, int out_size)
{
    const float* x    = (const float*)d_in[0];
    const float* tt   = (const float*)d_in[1];
    const float* yy   = (const float*)d_in[2];
    const float* Bprm = (const float*)d_in[3];
    const float* Win  = (const float*)d_in[4];
    const float* bin  = (const float*)d_in[5];
    const float* WT1  = (const float*)d_in[6];
    const float* bT1  = (const float*)d_in[7];
    const float* wT2  = (const float*)d_in[8];
    const float* bT2  = (const float*)d_in[9];
    const float* WY1  = (const float*)d_in[10];
    const float* bY1  = (const float*)d_in[11];
    const float* wY2  = (const float*)d_in[12];
    const float* bY2  = (const float*)d_in[13];
    float* out = (float*)d_out;

    // 102 c_s blocks + ceil((7168+16384)/128)=184 fragment blocks
    prep_kernel<<<286, 128>>>(Bprm, Win, WT1, WY1);
    fused_kernel<<<NBLK, THREADS>>>(
        x, tt, yy, bin,
        bT1, wT2, bT2,
        bY1, wY2, bY2, Bprm, out);
}

// round 9
// speedup vs baseline: 7.7329x; 1.1676x over previous
#include <cuda_runtime.h>
#include <cuda_fp16.h>
#include <cstdint>

// ---------------------------------------------------------------------------
// GNN_EBM reduced form:
//   out[b] = MLP_T(c100 * r0[b]) + MLP_Y(c101 * r0[b]),
//   r0 = relu(z @ Win^T + bin),  z = [x|t|y], c_i from sigmoid(B)*mask rowsums.
//
// Round-9: pure fp16 tensor-core path (precision budget: threshold 1e-3,
// predicted rel_err ~1e-4). Weights pre-packed into per-lane MMA fragments
// (uint2); ALL weight LDGs hoisted into registers (stage-A at entry, stage-B
// before the handoff barrier) so global latency overlaps fill/barrier phases.
// Per 16-k chunk: 1 ldmatrix.x4 + 1 m16n8k16 MMA. Dual accumulators halve
// the MMA dependency chain.
// ---------------------------------------------------------------------------

#define DX      100
#define DN      102
#define HID     256
#define MH      128
#define BT      16             // batch rows per block
#define NBLK    128
#define THREADS 1024
#define NCA     7              // stage-A chunks (16 k each)
#define NCB     16             // stage-B chunks

#define ZSW     60             // z row stride in 4B words (per-phase bank-clean)
#define RSW     132            // r0 row stride in words

__device__ float g_c_s[DN];                          // s[j] = rowsum_j(A)/N
__device__ __align__(16) uint2 g_fA[32 * NCA * 32];  // [tile][chunk][lane]
__device__ __align__(16) uint2 g_fB[32 * NCB * 32];  // [br*16+wb][chunk][lane]

__device__ __forceinline__ float sigm(float v) {
    return 1.0f / (1.0f + __expf(-v));
}

__device__ __forceinline__ void mma16(float* c, const uint32_t* a,
                                      uint32_t b0, uint32_t b1) {
    asm volatile(
        "mma.sync.aligned.m16n8k16.row.col.f32.f16.f16.f32 "
        "{%0,%1,%2,%3},{%4,%5,%6,%7},{%8,%9},{%0,%1,%2,%3};"
        : "+f"(c[0]), "+f"(c[1]), "+f"(c[2]), "+f"(c[3])
        : "r"(a[0]), "r"(a[1]), "r"(a[2]), "r"(a[3]), "r"(b0), "r"(b1));
}

__device__ __forceinline__ void ldsm4(uint32_t* r, uint32_t saddr) {
    asm volatile(
        "ldmatrix.sync.aligned.m8n8.x4.shared.b16 {%0,%1,%2,%3}, [%4];"
        : "=r"(r[0]), "=r"(r[1]), "=r"(r[2]), "=r"(r[3]) : "r"(saddr));
}

__device__ __forceinline__ uint32_t smem_u32(const void* p) {
    return (uint32_t)__cvta_generic_to_shared(p);
}

__device__ __forceinline__ uint32_t pack_h2(float v0, float v1) {
    __half h0 = __float2half_rn(v0), h1 = __float2half_rn(v1);
    return (uint32_t)__half_as_ushort(h0)
         | ((uint32_t)__half_as_ushort(h1) << 16);
}

// ---------------------------------------------------------------------------
// K1 prep (286 blocks x 128 threads):
//   blocks 0..101 : g_c_s[b]
//   blocks 102..  : fragment-pack weights (fp16 hi pairs) -> g_fA, g_fB
// ---------------------------------------------------------------------------
__global__ __launch_bounds__(128) void prep_kernel(
    const float* __restrict__ B,   const float* __restrict__ Win,
    const float* __restrict__ WT1, const float* __restrict__ WY1)
{
    const int b = blockIdx.x;
    const int t = threadIdx.x;

    if (b < DN) {
        __shared__ float wsum[4];
        int k = t;
        float v = 0.0f;
        bool valid = (b == DN - 1) ? (k == DN - 2) : (k < DN && k != b);
        if (valid) v = sigm(B[b * DN + k]);
        #pragma unroll
        for (int off = 16; off > 0; off >>= 1)
            v += __shfl_xor_sync(0xFFFFFFFFu, v, off);
        if ((t & 31) == 0) wsum[t >> 5] = v;
        __syncthreads();
        if (t == 0)
            g_c_s[b] = (wsum[0] + wsum[1] + wsum[2] + wsum[3]) / (float)DN;
        return;
    }

    int fid = (b - DN) * 128 + t;
    if (fid < 32 * NCA * 32) {
        int nt   = fid / (NCA * 32);
        int rem  = fid - nt * (NCA * 32);
        int g    = rem >> 5;
        int lane = rem & 31;
        int h  = 8 * nt + (lane >> 2);
        int k0 = 16 * g + 2 * (lane & 3);
        const float* wr = Win + h * DN;
        float v0 = (k0     < DN) ? wr[k0]     : 0.0f;
        float v1 = (k0 + 1 < DN) ? wr[k0 + 1] : 0.0f;
        float v2 = (k0 + 8 < DN) ? wr[k0 + 8] : 0.0f;
        float v3 = (k0 + 9 < DN) ? wr[k0 + 9] : 0.0f;
        uint2 o;
        o.x = pack_h2(v0, v1);
        o.y = pack_h2(v2, v3);
        g_fA[fid] = o;
        return;
    }

    int fid2 = fid - 32 * NCA * 32;
    if (fid2 < 32 * NCB * 32) {
        int tile = fid2 / (NCB * 32);   // br*16 + wb
        int rem  = fid2 - tile * (NCB * 32);
        int j    = rem >> 5;
        int lane = rem & 31;
        const float* W = (tile >> 4) ? WY1 : WT1;
        int h  = 8 * (tile & 15) + (lane >> 2);
        int k0 = 16 * j + 2 * (lane & 3);
        const float* wr = W + h * HID;
        uint2 o;
        o.x = pack_h2(wr[k0],     wr[k0 + 1]);
        o.y = pack_h2(wr[k0 + 8], wr[k0 + 9]);
        g_fB[fid2] = o;
    }
}

// ---------------------------------------------------------------------------
// K2 fused: 1024 threads (32 warps), BT=16 rows/block.
// Warp w: stage A n-tile = cols [8w, 8w+8); stage B: branch w>>4, cols 8*(w&15).
// ---------------------------------------------------------------------------
__global__ __launch_bounds__(THREADS, 1) void fused_kernel(
    const float* __restrict__ x,   const float* __restrict__ tt,
    const float* __restrict__ yy,  const float* __restrict__ bin,
    const float* __restrict__ bT1, const float* __restrict__ wT2,
    const float* __restrict__ bT2,
    const float* __restrict__ bY1, const float* __restrict__ wY2,
    const float* __restrict__ bY2,
    const float* __restrict__ Bp,
    float* __restrict__ out)
{
    __shared__ __align__(16) uint32_t zh[BT * ZSW];
    __shared__ __align__(16) uint32_t r0h[BT * RSW];
    __shared__ float red[16];
    __shared__ float accc[2];

    const int t    = threadIdx.x;
    const int w    = t >> 5;
    const int lane = t & 31;
    const int grp  = lane >> 2;
    const int qid  = lane & 3;
    const int b0   = blockIdx.x * BT;

    const int brB = w >> 4;       // stage-B branch (0=T, 1=Y)
    const int wb_ = w & 15;

    // ---- hoist ALL stage-A weights into registers (latency overlaps fill) ----
    uint2 wA[NCA];
    {
        const uint2* fA = g_fA + (w * NCA) * 32 + lane;
        #pragma unroll
        for (int g = 0; g < NCA; g++) wA[g] = __ldg(fA + g * 32);
    }

    if (t < 16) red[t] = 0.0f;
    if (t < 2)  accc[t] = 0.0f;

    // ---- fill z tile as fp16 pairs (pads zero) ----
    for (int idx = t; idx < BT * ZSW; idx += THREADS) {
        int r  = idx / ZSW;
        int kw = idx - r * ZSW;
        int b  = b0 + r;
        float v0 = 0.0f, v1 = 0.0f;
        int k0 = 2 * kw;
        if (k0 < DX)            v0 = x[b * DX + k0];
        else if (k0 == DX)      v0 = tt[b];
        else if (k0 == DX + 1)  v0 = yy[b];
        int k1 = k0 + 1;
        if (k1 < DX)            v1 = x[b * DX + k1];
        else if (k1 == DX)      v1 = tt[b];
        else if (k1 == DX + 1)  v1 = yy[b];
        zh[idx] = pack_h2(v0, v1);
    }
    __syncthreads();

    // ---- c partial sums (consumed after the handoff barrier) ----
    if (t < DN && t != DN - 2)
        atomicAdd(&accc[0], sigm(Bp[(DN - 2) * DN + t]) * (1.0f + g_c_s[t]));
    if (t == 0)
        atomicAdd(&accc[1],
                  sigm(Bp[(DN - 1) * DN + (DN - 2)]) * (1.0f + g_c_s[DN - 2]));

    // ldmatrix per-lane source addresses
    const int arow = lane & 15;
    const int acol = (lane >> 4) * 4;
    const uint32_t zh_a  = smem_u32(zh)  + (arow * ZSW + acol) * 4;
    const uint32_t r0h_a = smem_u32(r0h) + (arow * RSW + acol) * 4;

    float accM[4], acc2[4];
    #pragma unroll
    for (int i = 0; i < 4; i++) { accM[i] = 0.0f; acc2[i] = 0.0f; }

    // ---- stage A: 7 chunks, dual accumulators ----
    #pragma unroll
    for (int g = 0; g < NCA; g++) {
        uint32_t ah[4];
        ldsm4(ah, zh_a + g * 32);
        mma16((g & 1) ? acc2 : accM, ah, wA[g].x, wA[g].y);
    }

    // ---- hoist ALL stage-B weights (latency overlaps epilogue + barrier) ----
    uint2 wB[NCB];
    {
        const uint2* fB = g_fB + ((brB * 16 + wb_) * NCB) * 32 + lane;
        #pragma unroll
        for (int j = 0; j < NCB; j++) wB[j] = __ldg(fB + j * 32);
    }

    // stage-A epilogue: bias, relu, pack -> r0h
    {
        int h0 = 8 * w + 2 * qid;
        float bi0 = bin[h0], bi1 = bin[h0 + 1];
        float v00 = fmaxf(accM[0] + acc2[0] + bi0, 0.0f);
        float v01 = fmaxf(accM[1] + acc2[1] + bi1, 0.0f);
        float v10 = fmaxf(accM[2] + acc2[2] + bi0, 0.0f);
        float v11 = fmaxf(accM[3] + acc2[3] + bi1, 0.0f);
        int wofs = 4 * w + qid;
        r0h[grp * RSW + wofs]       = pack_h2(v00, v01);
        r0h[(grp + 8) * RSW + wofs] = pack_h2(v10, v11);
    }

    __syncthreads();   // r0 handoff

    #pragma unroll
    for (int i = 0; i < 4; i++) { accM[i] = 0.0f; acc2[i] = 0.0f; }

    // ---- stage B: 16 chunks, dual accumulators ----
    #pragma unroll
    for (int j = 0; j < NCB; j++) {
        uint32_t ah[4];
        ldsm4(ah, r0h_a + j * 32);
        mma16((j & 1) ? acc2 : accM, ah, wB[j].x, wB[j].y);
    }

    // ---- stage-B epilogue: c-scale, bias, relu, dot w2, reduce ----
    {
        const float* b1p = brB ? bY1 : bT1;
        const float* w2p = brB ? wY2 : wT2;
        const float  cs  = 1.0f + g_c_s[DN - 2 + brB] + accc[brB] / (float)DN;

        int h0 = 8 * wb_ + 2 * qid;
        float b10 = b1p[h0], b11 = b1p[h0 + 1];
        float w20 = w2p[h0], w21 = w2p[h0 + 1];
        float m, sl = 0.0f, sh = 0.0f;
        m = fmaxf(fmaf(cs, accM[0] + acc2[0], b10), 0.0f); sl = fmaf(m, w20, sl);
        m = fmaxf(fmaf(cs, accM[1] + acc2[1], b11), 0.0f); sl = fmaf(m, w21, sl);
        m = fmaxf(fmaf(cs, accM[2] + acc2[2], b10), 0.0f); sh = fmaf(m, w20, sh);
        m = fmaxf(fmaf(cs, accM[3] + acc2[3], b11), 0.0f); sh = fmaf(m, w21, sh);
        sl += __shfl_xor_sync(0xFFFFFFFFu, sl, 1);
        sl += __shfl_xor_sync(0xFFFFFFFFu, sl, 2);
        sh += __shfl_xor_sync(0xFFFFFFFFu, sh, 1);
        sh += __shfl_xor_sync(0xFFFFFFFFu, sh, 2);
        if (qid == 0) {
            atomicAdd(&red[grp], sl);
            atomicAdd(&red[grp + 8], sh);
        }
    }
    __syncthreads();

    if (t < BT)
        out[b0 + t] = red[t] + bT2[0] + bY2[0];
}

// ---------------------------------------------------------------------------
extern "C" void kernel_launch(void* const* d_in, const int* in_sizes, int n_in,
                              void* d_out, int out_size)
{
    const float* x    = (const float*)d_in[0];
    const float* tt   = (const float*)d_in[1];
    const float* yy   = (const float*)d_in[2];
    const float* Bprm = (const float*)d_in[3];
    const float* Win  = (const float*)d_in[4];
    const float* bin  = (const float*)d_in[5];
    const float* WT1  = (const float*)d_in[6];
    const float* bT1  = (const float*)d_in[7];
    const float* wT2  = (const float*)d_in[8];
    const float* bT2  = (const float*)d_in[9];
    const float* WY1  = (const float*)d_in[10];
    const float* bY1  = (const float*)d_in[11];
    const float* wY2  = (const float*)d_in[12];
    const float* bY2  = (const float*)d_in[13];
    float* out = (float*)d_out;

    prep_kernel<<<286, 128>>>(Bprm, Win, WT1, WY1);
    fused_kernel<<<NBLK, THREADS>>>(
        x, tt, yy, bin,
        bT1, wT2, bT2,
        bY1, wY2, bY2, Bprm, out);
}

// round 10
// speedup vs baseline: 8.8352x; 1.1425x over previous
#include <cuda_runtime.h>
#include <cuda_fp16.h>
#include <cstdint>

// ---------------------------------------------------------------------------
// GNN_EBM reduced form:
//   out[b] = MLP_T(c100 * r0[b]) + MLP_Y(c101 * r0[b]),
//   r0 = relu(z @ Win^T + bin),  z = [x|t|y], c_i from sigmoid(B)*mask rowsums.
//
// Round-10 (on top of R9's pure-fp16 fragment path):
//  * software-pipelined ldmatrix (ping-pong) in both MMA stages
//  * prep pre-fills out[b] = bT2+bY2; fused writes via direct atomicAdd
//    (removes 3rd barrier + serialized output tail)
// ---------------------------------------------------------------------------

#define DX      100
#define DN      102
#define HID     256
#define MH      128
#define BT      16             // batch rows per block
#define NBLK    128
#define BATCH   2048
#define THREADS 1024
#define NCA     7              // stage-A chunks (16 k each)
#define NCB     16             // stage-B chunks

#define ZSW     60             // z row stride in 4B words
#define RSW     132            // r0 row stride in words

#define NFRAG_A (32 * NCA * 32)     // 7168
#define NFRAG_B (32 * NCB * 32)     // 16384
#define PREP_FRAG_BLOCKS 184        // ceil((7168+16384)/128)
#define PREP_OUT_BLOCKS  (BATCH / 128)   // 16

__device__ float g_c_s[DN];                          // s[j] = rowsum_j(A)/N
__device__ __align__(16) uint2 g_fA[NFRAG_A];        // [tile][chunk][lane]
__device__ __align__(16) uint2 g_fB[NFRAG_B];        // [br*16+wb][chunk][lane]

__device__ __forceinline__ float sigm(float v) {
    return 1.0f / (1.0f + __expf(-v));
}

__device__ __forceinline__ void mma16(float* c, const uint32_t* a,
                                      uint32_t b0, uint32_t b1) {
    asm volatile(
        "mma.sync.aligned.m16n8k16.row.col.f32.f16.f16.f32 "
        "{%0,%1,%2,%3},{%4,%5,%6,%7},{%8,%9},{%0,%1,%2,%3};"
        : "+f"(c[0]), "+f"(c[1]), "+f"(c[2]), "+f"(c[3])
        : "r"(a[0]), "r"(a[1]), "r"(a[2]), "r"(a[3]), "r"(b0), "r"(b1));
}

__device__ __forceinline__ void ldsm4(uint32_t* r, uint32_t saddr) {
    asm volatile(
        "ldmatrix.sync.aligned.m8n8.x4.shared.b16 {%0,%1,%2,%3}, [%4];"
        : "=r"(r[0]), "=r"(r[1]), "=r"(r[2]), "=r"(r[3]) : "r"(saddr));
}

__device__ __forceinline__ uint32_t smem_u32(const void* p) {
    return (uint32_t)__cvta_generic_to_shared(p);
}

__device__ __forceinline__ uint32_t pack_h2(float v0, float v1) {
    __half h0 = __float2half_rn(v0), h1 = __float2half_rn(v1);
    return (uint32_t)__half_as_ushort(h0)
         | ((uint32_t)__half_as_ushort(h1) << 16);
}

// ---------------------------------------------------------------------------
// K1 prep (302 blocks x 128 threads):
//   blocks 0..101  : g_c_s[b]
//   blocks 102..285: fragment-pack weights -> g_fA, g_fB
//   blocks 286..301: out[b] = bT2[0] + bY2[0]
// ---------------------------------------------------------------------------
__global__ __launch_bounds__(128) void prep_kernel(
    const float* __restrict__ B,   const float* __restrict__ Win,
    const float* __restrict__ WT1, const float* __restrict__ WY1,
    const float* __restrict__ bT2, const float* __restrict__ bY2,
    float* __restrict__ out)
{
    const int b = blockIdx.x;
    const int t = threadIdx.x;

    if (b < DN) {
        __shared__ float wsum[4];
        int k = t;
        float v = 0.0f;
        bool valid = (b == DN - 1) ? (k == DN - 2) : (k < DN && k != b);
        if (valid) v = sigm(B[b * DN + k]);
        #pragma unroll
        for (int off = 16; off > 0; off >>= 1)
            v += __shfl_xor_sync(0xFFFFFFFFu, v, off);
        if ((t & 31) == 0) wsum[t >> 5] = v;
        __syncthreads();
        if (t == 0)
            g_c_s[b] = (wsum[0] + wsum[1] + wsum[2] + wsum[3]) / (float)DN;
        return;
    }

    if (b >= DN + PREP_FRAG_BLOCKS) {
        // out prefill
        int idx = (b - DN - PREP_FRAG_BLOCKS) * 128 + t;
        if (idx < BATCH) out[idx] = bT2[0] + bY2[0];
        return;
    }

    int fid = (b - DN) * 128 + t;
    if (fid < NFRAG_A) {
        int nt   = fid / (NCA * 32);
        int rem  = fid - nt * (NCA * 32);
        int g    = rem >> 5;
        int lane = rem & 31;
        int h  = 8 * nt + (lane >> 2);
        int k0 = 16 * g + 2 * (lane & 3);
        const float* wr = Win + h * DN;
        float v0 = (k0     < DN) ? wr[k0]     : 0.0f;
        float v1 = (k0 + 1 < DN) ? wr[k0 + 1] : 0.0f;
        float v2 = (k0 + 8 < DN) ? wr[k0 + 8] : 0.0f;
        float v3 = (k0 + 9 < DN) ? wr[k0 + 9] : 0.0f;
        uint2 o;
        o.x = pack_h2(v0, v1);
        o.y = pack_h2(v2, v3);
        g_fA[fid] = o;
        return;
    }

    int fid2 = fid - NFRAG_A;
    if (fid2 < NFRAG_B) {
        int tile = fid2 / (NCB * 32);   // br*16 + wb
        int rem  = fid2 - tile * (NCB * 32);
        int j    = rem >> 5;
        int lane = rem & 31;
        const float* W = (tile >> 4) ? WY1 : WT1;
        int h  = 8 * (tile & 15) + (lane >> 2);
        int k0 = 16 * j + 2 * (lane & 3);
        const float* wr = W + h * HID;
        uint2 o;
        o.x = pack_h2(wr[k0],     wr[k0 + 1]);
        o.y = pack_h2(wr[k0 + 8], wr[k0 + 9]);
        g_fB[fid2] = o;
    }
}

// ---------------------------------------------------------------------------
// K2 fused: 1024 threads (32 warps), BT=16 rows/block.
// Warp w: stage A n-tile = cols [8w, 8w+8); stage B: branch w>>4, cols 8*(w&15).
// ---------------------------------------------------------------------------
__global__ __launch_bounds__(THREADS, 1) void fused_kernel(
    const float* __restrict__ x,   const float* __restrict__ tt,
    const float* __restrict__ yy,  const float* __restrict__ bin,
    const float* __restrict__ bT1, const float* __restrict__ wT2,
    const float* __restrict__ bY1, const float* __restrict__ wY2,
    const float* __restrict__ Bp,
    float* __restrict__ out)
{
    __shared__ __align__(16) uint32_t zh[BT * ZSW];
    __shared__ __align__(16) uint32_t r0h[BT * RSW];
    __shared__ float accc[2];

    const int t    = threadIdx.x;
    const int w    = t >> 5;
    const int lane = t & 31;
    const int grp  = lane >> 2;
    const int qid  = lane & 3;
    const int b0   = blockIdx.x * BT;

    const int brB = w >> 4;       // stage-B branch (0=T, 1=Y)
    const int wb_ = w & 15;

    // ---- hoist ALL stage-A weights into registers ----
    uint2 wA[NCA];
    {
        const uint2* fA = g_fA + (w * NCA) * 32 + lane;
        #pragma unroll
        for (int g = 0; g < NCA; g++) wA[g] = __ldg(fA + g * 32);
    }

    if (t < 2) accc[t] = 0.0f;

    // ---- fill z tile as fp16 pairs (pads zero) ----
    for (int idx = t; idx < BT * ZSW; idx += THREADS) {
        int r  = idx / ZSW;
        int kw = idx - r * ZSW;
        int b  = b0 + r;
        float v0 = 0.0f, v1 = 0.0f;
        int k0 = 2 * kw;
        if (k0 < DX)            v0 = x[b * DX + k0];
        else if (k0 == DX)      v0 = tt[b];
        else if (k0 == DX + 1)  v0 = yy[b];
        int k1 = k0 + 1;
        if (k1 < DX)            v1 = x[b * DX + k1];
        else if (k1 == DX)      v1 = tt[b];
        else if (k1 == DX + 1)  v1 = yy[b];
        zh[idx] = pack_h2(v0, v1);
    }
    __syncthreads();

    // ---- c partial sums (consumed after the handoff barrier) ----
    if (t < DN && t != DN - 2)
        atomicAdd(&accc[0], sigm(Bp[(DN - 2) * DN + t]) * (1.0f + g_c_s[t]));
    if (t == 0)
        atomicAdd(&accc[1],
                  sigm(Bp[(DN - 1) * DN + (DN - 2)]) * (1.0f + g_c_s[DN - 2]));

    // ldmatrix per-lane source addresses
    const int arow = lane & 15;
    const int acol = (lane >> 4) * 4;
    const uint32_t zh_a  = smem_u32(zh)  + (arow * ZSW + acol) * 4;
    const uint32_t r0h_a = smem_u32(r0h) + (arow * RSW + acol) * 4;

    float accM[4], acc2[4];
    #pragma unroll
    for (int i = 0; i < 4; i++) { accM[i] = 0.0f; acc2[i] = 0.0f; }

    // ---- stage A: 7 chunks, ping-pong ldsm, dual accumulators ----
    {
        uint32_t fa[4], fb[4];
        ldsm4(fa, zh_a);
        #pragma unroll
        for (int g = 0; g < NCA; g++) {
            uint32_t* cur = (g & 1) ? fb : fa;
            uint32_t* nxt = (g & 1) ? fa : fb;
            if (g + 1 < NCA) ldsm4(nxt, zh_a + (g + 1) * 32);
            mma16((g & 1) ? acc2 : accM, cur, wA[g].x, wA[g].y);
        }
    }

    // ---- hoist ALL stage-B weights (overlaps epilogue + barrier) ----
    uint2 wB[NCB];
    {
        const uint2* fB = g_fB + ((brB * 16 + wb_) * NCB) * 32 + lane;
        #pragma unroll
        for (int j = 0; j < NCB; j++) wB[j] = __ldg(fB + j * 32);
    }

    // stage-A epilogue: bias, relu, pack -> r0h
    {
        int h0 = 8 * w + 2 * qid;
        float bi0 = bin[h0], bi1 = bin[h0 + 1];
        float v00 = fmaxf(accM[0] + acc2[0] + bi0, 0.0f);
        float v01 = fmaxf(accM[1] + acc2[1] + bi1, 0.0f);
        float v10 = fmaxf(accM[2] + acc2[2] + bi0, 0.0f);
        float v11 = fmaxf(accM[3] + acc2[3] + bi1, 0.0f);
        int wofs = 4 * w + qid;
        r0h[grp * RSW + wofs]       = pack_h2(v00, v01);
        r0h[(grp + 8) * RSW + wofs] = pack_h2(v10, v11);
    }

    __syncthreads();   // r0 handoff

    #pragma unroll
    for (int i = 0; i < 4; i++) { accM[i] = 0.0f; acc2[i] = 0.0f; }

    // ---- stage B: 16 chunks, ping-pong ldsm, dual accumulators ----
    {
        uint32_t fa[4], fb[4];
        ldsm4(fa, r0h_a);
        #pragma unroll
        for (int j = 0; j < NCB; j++) {
            uint32_t* cur = (j & 1) ? fb : fa;
            uint32_t* nxt = (j & 1) ? fa : fb;
            if (j + 1 < NCB) ldsm4(nxt, r0h_a + (j + 1) * 32);
            mma16((j & 1) ? acc2 : accM, cur, wB[j].x, wB[j].y);
        }
    }

    // ---- stage-B epilogue: c-scale, bias, relu, dot w2, direct atomics ----
    {
        const float* b1p = brB ? bY1 : bT1;
        const float* w2p = brB ? wY2 : wT2;
        const float  cs  = 1.0f + g_c_s[DN - 2 + brB] + accc[brB] / (float)DN;

        int h0 = 8 * wb_ + 2 * qid;
        float b10 = b1p[h0], b11 = b1p[h0 + 1];
        float w20 = w2p[h0], w21 = w2p[h0 + 1];
        float m, sl = 0.0f, sh = 0.0f;
        m = fmaxf(fmaf(cs, accM[0] + acc2[0], b10), 0.0f); sl = fmaf(m, w20, sl);
        m = fmaxf(fmaf(cs, accM[1] + acc2[1], b11), 0.0f); sl = fmaf(m, w21, sl);
        m = fmaxf(fmaf(cs, accM[2] + acc2[2], b10), 0.0f); sh = fmaf(m, w20, sh);
        m = fmaxf(fmaf(cs, accM[3] + acc2[3], b11), 0.0f); sh = fmaf(m, w21, sh);
        sl += __shfl_xor_sync(0xFFFFFFFFu, sl, 1);
        sl += __shfl_xor_sync(0xFFFFFFFFu, sl, 2);
        sh += __shfl_xor_sync(0xFFFFFFFFu, sh, 1);
        sh += __shfl_xor_sync(0xFFFFFFFFu, sh, 2);
        if (qid == 0) {
            atomicAdd(out + b0 + grp,     sl);   // out prefilled with bT2+bY2
            atomicAdd(out + b0 + grp + 8, sh);
        }
    }
}

// ---------------------------------------------------------------------------
extern "C" void kernel_launch(void* const* d_in, const int* in_sizes, int n_in,
                              void* d_out, int out_size)
{
    const float* x    = (const float*)d_in[0];
    const float* tt   = (const float*)d_in[1];
    const float* yy   = (const float*)d_in[2];
    const float* Bprm = (const float*)d_in[3];
    const float* Win  = (const float*)d_in[4];
    const float* bin  = (const float*)d_in[5];
    const float* WT1  = (const float*)d_in[6];
    const float* bT1  = (const float*)d_in[7];
    const float* wT2  = (const float*)d_in[8];
    const float* bT2  = (const float*)d_in[9];
    const float* WY1  = (const float*)d_in[10];
    const float* bY1  = (const float*)d_in[11];
    const float* wY2  = (const float*)d_in[12];
    const float* bY2  = (const float*)d_in[13];
    float* out = (float*)d_out;

    prep_kernel<<<DN + PREP_FRAG_BLOCKS + PREP_OUT_BLOCKS, 128>>>(
        Bprm, Win, WT1, WY1, bT2, bY2, out);
    fused_kernel<<<NBLK, THREADS>>>(
        x, tt, yy, bin,
        bT1, wT2,
        bY1, wY2, Bprm, out);
}

// round 11
// speedup vs baseline: 11.9849x; 1.3565x over previous
#include <cuda_runtime.h>
#include <cuda_fp16.h>
#include <cstdint>

// ---------------------------------------------------------------------------
// GNN_EBM reduced form:
//   out[b] = MLP_T(c100 * r0[b]) + MLP_Y(c101 * r0[b]),
//   r0 = relu(z @ Win^T + bin),  z = [x|t|y], c_i from sigmoid(B)*mask rowsums.
//
// Round-11 (on R10's fp16 fragment path):
//  * stage-B weights: rolling register prefetch (distance 4) instead of a
//    32-reg full hoist -> peak pressure under the 64-reg/1024-thread cap,
//    no spills.
//  * c partial sums via warp-reduce + 4 atomics (was 101 same-address ATOMS).
// ---------------------------------------------------------------------------

#define DX      100
#define DN      102
#define HID     256
#define MH      128
#define BT      16             // batch rows per block
#define NBLK    128
#define BATCH   2048
#define THREADS 1024
#define NCA     7              // stage-A chunks (16 k each)
#define NCB     16             // stage-B chunks

#define ZSW     60             // z row stride in 4B words (conflict-free ldsm)
#define RSW     132            // r0 row stride in words  (conflict-free ldsm)

#define NFRAG_A (32 * NCA * 32)     // 7168
#define NFRAG_B (32 * NCB * 32)     // 16384
#define PREP_FRAG_BLOCKS 184        // ceil((7168+16384)/128)
#define PREP_OUT_BLOCKS  (BATCH / 128)   // 16

__device__ float g_c_s[DN];                          // s[j] = rowsum_j(A)/N
__device__ __align__(16) uint2 g_fA[NFRAG_A];        // [tile][chunk][lane]
__device__ __align__(16) uint2 g_fB[NFRAG_B];        // [br*16+wb][chunk][lane]

__device__ __forceinline__ float sigm(float v) {
    return 1.0f / (1.0f + __expf(-v));
}

__device__ __forceinline__ void mma16(float* c, const uint32_t* a,
                                      uint32_t b0, uint32_t b1) {
    asm volatile(
        "mma.sync.aligned.m16n8k16.row.col.f32.f16.f16.f32 "
        "{%0,%1,%2,%3},{%4,%5,%6,%7},{%8,%9},{%0,%1,%2,%3};"
        : "+f"(c[0]), "+f"(c[1]), "+f"(c[2]), "+f"(c[3])
        : "r"(a[0]), "r"(a[1]), "r"(a[2]), "r"(a[3]), "r"(b0), "r"(b1));
}

__device__ __forceinline__ void ldsm4(uint32_t* r, uint32_t saddr) {
    asm volatile(
        "ldmatrix.sync.aligned.m8n8.x4.shared.b16 {%0,%1,%2,%3}, [%4];"
        : "=r"(r[0]), "=r"(r[1]), "=r"(r[2]), "=r"(r[3]) : "r"(saddr));
}

__device__ __forceinline__ uint32_t smem_u32(const void* p) {
    return (uint32_t)__cvta_generic_to_shared(p);
}

__device__ __forceinline__ uint32_t pack_h2(float v0, float v1) {
    __half h0 = __float2half_rn(v0), h1 = __float2half_rn(v1);
    return (uint32_t)__half_as_ushort(h0)
         | ((uint32_t)__half_as_ushort(h1) << 16);
}

// ---------------------------------------------------------------------------
// K1 prep (302 blocks x 128 threads):
//   blocks 0..101  : g_c_s[b]
//   blocks 102..285: fragment-pack weights -> g_fA, g_fB
//   blocks 286..301: out[b] = bT2[0] + bY2[0]
// ---------------------------------------------------------------------------
__global__ __launch_bounds__(128) void prep_kernel(
    const float* __restrict__ B,   const float* __restrict__ Win,
    const float* __restrict__ WT1, const float* __restrict__ WY1,
    const float* __restrict__ bT2, const float* __restrict__ bY2,
    float* __restrict__ out)
{
    const int b = blockIdx.x;
    const int t = threadIdx.x;

    if (b < DN) {
        __shared__ float wsum[4];
        int k = t;
        float v = 0.0f;
        bool valid = (b == DN - 1) ? (k == DN - 2) : (k < DN && k != b);
        if (valid) v = sigm(B[b * DN + k]);
        #pragma unroll
        for (int off = 16; off > 0; off >>= 1)
            v += __shfl_xor_sync(0xFFFFFFFFu, v, off);
        if ((t & 31) == 0) wsum[t >> 5] = v;
        __syncthreads();
        if (t == 0)
            g_c_s[b] = (wsum[0] + wsum[1] + wsum[2] + wsum[3]) / (float)DN;
        return;
    }

    if (b >= DN + PREP_FRAG_BLOCKS) {
        int idx = (b - DN - PREP_FRAG_BLOCKS) * 128 + t;
        if (idx < BATCH) out[idx] = bT2[0] + bY2[0];
        return;
    }

    int fid = (b - DN) * 128 + t;
    if (fid < NFRAG_A) {
        int nt   = fid / (NCA * 32);
        int rem  = fid - nt * (NCA * 32);
        int g    = rem >> 5;
        int lane = rem & 31;
        int h  = 8 * nt + (lane >> 2);
        int k0 = 16 * g + 2 * (lane & 3);
        const float* wr = Win + h * DN;
        float v0 = (k0     < DN) ? wr[k0]     : 0.0f;
        float v1 = (k0 + 1 < DN) ? wr[k0 + 1] : 0.0f;
        float v2 = (k0 + 8 < DN) ? wr[k0 + 8] : 0.0f;
        float v3 = (k0 + 9 < DN) ? wr[k0 + 9] : 0.0f;
        uint2 o;
        o.x = pack_h2(v0, v1);
        o.y = pack_h2(v2, v3);
        g_fA[fid] = o;
        return;
    }

    int fid2 = fid - NFRAG_A;
    if (fid2 < NFRAG_B) {
        int tile = fid2 / (NCB * 32);   // br*16 + wb
        int rem  = fid2 - tile * (NCB * 32);
        int j    = rem >> 5;
        int lane = rem & 31;
        const float* W = (tile >> 4) ? WY1 : WT1;
        int h  = 8 * (tile & 15) + (lane >> 2);
        int k0 = 16 * j + 2 * (lane & 3);
        const float* wr = W + h * HID;
        uint2 o;
        o.x = pack_h2(wr[k0],     wr[k0 + 1]);
        o.y = pack_h2(wr[k0 + 8], wr[k0 + 9]);
        g_fB[fid2] = o;
    }
}

// ---------------------------------------------------------------------------
// K2 fused: 1024 threads (32 warps), BT=16 rows/block.
// Warp w: stage A n-tile = cols [8w, 8w+8); stage B: branch w>>4, cols 8*(w&15).
// ---------------------------------------------------------------------------
__global__ __launch_bounds__(THREADS, 1) void fused_kernel(
    const float* __restrict__ x,   const float* __restrict__ tt,
    const float* __restrict__ yy,  const float* __restrict__ bin,
    const float* __restrict__ bT1, const float* __restrict__ wT2,
    const float* __restrict__ bY1, const float* __restrict__ wY2,
    const float* __restrict__ Bp,
    float* __restrict__ out)
{
    __shared__ __align__(16) uint32_t zh[BT * ZSW];
    __shared__ __align__(16) uint32_t r0h[BT * RSW];
    __shared__ float accc[2];

    const int t    = threadIdx.x;
    const int w    = t >> 5;
    const int lane = t & 31;
    const int grp  = lane >> 2;
    const int qid  = lane & 3;
    const int b0   = blockIdx.x * BT;

    const int brB = w >> 4;       // stage-B branch (0=T, 1=Y)
    const int wb_ = w & 15;

    // ---- hoist stage-A weights into registers (7 x uint2) ----
    uint2 wA[NCA];
    {
        const uint2* fA = g_fA + (w * NCA) * 32 + lane;
        #pragma unroll
        for (int g = 0; g < NCA; g++) wA[g] = __ldg(fA + g * 32);
    }

    if (t < 2) accc[t] = 0.0f;

    // ---- fill z tile as fp16 pairs (pads zero) ----
    for (int idx = t; idx < BT * ZSW; idx += THREADS) {
        int r  = idx / ZSW;
        int kw = idx - r * ZSW;
        int b  = b0 + r;
        float v0 = 0.0f, v1 = 0.0f;
        int k0 = 2 * kw;
        if (k0 < DX)            v0 = x[b * DX + k0];
        else if (k0 == DX)      v0 = tt[b];
        else if (k0 == DX + 1)  v0 = yy[b];
        int k1 = k0 + 1;
        if (k1 < DX)            v1 = x[b * DX + k1];
        else if (k1 == DX)      v1 = tt[b];
        else if (k1 == DX + 1)  v1 = yy[b];
        zh[idx] = pack_h2(v0, v1);
    }
    __syncthreads();

    // ---- c partial sums: per-warp shfl reduce + 1 atomic/warp ----
    if (w < 4) {
        int j = t;   // 0..127
        float v = 0.0f;
        if (j < DN && j != DN - 2)
            v = sigm(Bp[(DN - 2) * DN + j]) * (1.0f + g_c_s[j]);
        #pragma unroll
        for (int off = 16; off > 0; off >>= 1)
            v += __shfl_xor_sync(0xFFFFFFFFu, v, off);
        if (lane == 0) atomicAdd(&accc[0], v);
        if (t == 0)
            atomicAdd(&accc[1],
                      sigm(Bp[(DN - 1) * DN + (DN - 2)]) * (1.0f + g_c_s[DN - 2]));
    }

    // ldmatrix per-lane source addresses
    const int arow = lane & 15;
    const int acol = (lane >> 4) * 4;
    const uint32_t zh_a  = smem_u32(zh)  + (arow * ZSW + acol) * 4;
    const uint32_t r0h_a = smem_u32(r0h) + (arow * RSW + acol) * 4;

    float accM[4], acc2[4];
    #pragma unroll
    for (int i = 0; i < 4; i++) { accM[i] = 0.0f; acc2[i] = 0.0f; }

    // ---- stage A: 7 chunks, ping-pong ldsm, dual accumulators ----
    {
        uint32_t fa[4], fb[4];
        ldsm4(fa, zh_a);
        #pragma unroll
        for (int g = 0; g < NCA; g++) {
            uint32_t* cur = (g & 1) ? fb : fa;
            uint32_t* nxt = (g & 1) ? fa : fb;
            if (g + 1 < NCA) ldsm4(nxt, zh_a + (g + 1) * 32);
            mma16((g & 1) ? acc2 : accM, cur, wA[g].x, wA[g].y);
        }
    }

    // ---- stage-B weights: rolling prefetch, distance 4 ----
    const uint2* fB = g_fB + ((brB * 16 + wb_) * NCB) * 32 + lane;
    uint2 wB[NCB];   // fully unrolled below -> ptxas keeps ~5 live
    #pragma unroll
    for (int j = 0; j < 4; j++) wB[j] = __ldg(fB + j * 32);

    // stage-A epilogue: bias, relu, pack -> r0h
    {
        int h0 = 8 * w + 2 * qid;
        float bi0 = bin[h0], bi1 = bin[h0 + 1];
        float v00 = fmaxf(accM[0] + acc2[0] + bi0, 0.0f);
        float v01 = fmaxf(accM[1] + acc2[1] + bi1, 0.0f);
        float v10 = fmaxf(accM[2] + acc2[2] + bi0, 0.0f);
        float v11 = fmaxf(accM[3] + acc2[3] + bi1, 0.0f);
        int wofs = 4 * w + qid;
        r0h[grp * RSW + wofs]       = pack_h2(v00, v01);
        r0h[(grp + 8) * RSW + wofs] = pack_h2(v10, v11);
    }

    __syncthreads();   // r0 handoff

    #pragma unroll
    for (int i = 0; i < 4; i++) { accM[i] = 0.0f; acc2[i] = 0.0f; }

    // ---- stage B: 16 chunks, ping-pong ldsm, rolling weight prefetch ----
    {
        uint32_t fa[4], fb[4];
        ldsm4(fa, r0h_a);
        #pragma unroll
        for (int j = 0; j < NCB; j++) {
            if (j + 4 < NCB) wB[j + 4] = __ldg(fB + (j + 4) * 32);
            uint32_t* cur = (j & 1) ? fb : fa;
            uint32_t* nxt = (j & 1) ? fa : fb;
            if (j + 1 < NCB) ldsm4(nxt, r0h_a + (j + 1) * 32);
            mma16((j & 1) ? acc2 : accM, cur, wB[j].x, wB[j].y);
        }
    }

    // ---- stage-B epilogue: c-scale, bias, relu, dot w2, direct atomics ----
    {
        const float* b1p = brB ? bY1 : bT1;
        const float* w2p = brB ? wY2 : wT2;
        const float  cs  = 1.0f + g_c_s[DN - 2 + brB] + accc[brB] / (float)DN;

        int h0 = 8 * wb_ + 2 * qid;
        float b10 = b1p[h0], b11 = b1p[h0 + 1];
        float w20 = w2p[h0], w21 = w2p[h0 + 1];
        float m, sl = 0.0f, sh = 0.0f;
        m = fmaxf(fmaf(cs, accM[0] + acc2[0], b10), 0.0f); sl = fmaf(m, w20, sl);
        m = fmaxf(fmaf(cs, accM[1] + acc2[1], b11), 0.0f); sl = fmaf(m, w21, sl);
        m = fmaxf(fmaf(cs, accM[2] + acc2[2], b10), 0.0f); sh = fmaf(m, w20, sh);
        m = fmaxf(fmaf(cs, accM[3] + acc2[3], b11), 0.0f); sh = fmaf(m, w21, sh);
        sl += __shfl_xor_sync(0xFFFFFFFFu, sl, 1);
        sl += __shfl_xor_sync(0xFFFFFFFFu, sl, 2);
        sh += __shfl_xor_sync(0xFFFFFFFFu, sh, 1);
        sh += __shfl_xor_sync(0xFFFFFFFFu, sh, 2);
        if (qid == 0) {
            atomicAdd(out + b0 + grp,     sl);   // out prefilled with bT2+bY2
            atomicAdd(out + b0 + grp + 8, sh);
        }
    }
}

// ---------------------------------------------------------------------------
extern "C" void kernel_launch(void* const* d_in, const int* in_sizes, int n_in,
                              void* d_out, int out_size)
{
    const float* x    = (const float*)d_in[0];
    const float* tt   = (const float*)d_in[1];
    const float* yy   = (const float*)d_in[2];
    const float* Bprm = (const float*)d_in[3];
    const float* Win  = (const float*)d_in[4];
    const float* bin  = (const float*)d_in[5];
    const float* WT1  = (const float*)d_in[6];
    const float* bT1  = (const float*)d_in[7];
    const float* wT2  = (const float*)d_in[8];
    const float* bT2  = (const float*)d_in[9];
    const float* WY1  = (const float*)d_in[10];
    const float* bY1  = (const float*)d_in[11];
    const float* wY2  = (const float*)d_in[12];
    const float* bY2  = (const float*)d_in[13];
    float* out = (float*)d_out;

    prep_kernel<<<DN + PREP_FRAG_BLOCKS + PREP_OUT_BLOCKS, 128>>>(
        Bprm, Win, WT1, WY1, bT2, bY2, out);
    fused_kernel<<<NBLK, THREADS>>>(
        x, tt, yy, bin,
        bT1, wT2,
        bY1, wY2, Bprm, out);
}